// round 1
// baseline (speedup 1.0000x reference)
#include <cuda_runtime.h>
#include <cuda_bf16.h>

// ---------------------------------------------------------------------------
// Problem constants
//   x: (4, 256, 256, 256) f32    HW = 65536 pixels, C = 256, B = 4
//   windows: 4x4 (ws=4), heads=8, d=32
// ---------------------------------------------------------------------------
#define B_   4
#define C_   256
#define H_   256
#define W_   256
#define HW_  65536
#define HEADS_ 8
#define DHEAD_ 32

// Scratch (device globals: allocation-free rule)
__device__ float d_qkv[(long long)B_ * 3 * C_ * HW_];  // 805 MB
__device__ float d_attn[(long long)B_ * C_ * HW_];     // 268 MB
__device__ float d_vg[(long long)B_ * C_ * HW_];       // 268 MB
__device__ float d_pre[(long long)B_ * C_ * HW_];      // 268 MB

// ---------------------------------------------------------------------------
// Generic SGEMM:  Y[b][m][p] = sum_k W[m][k] * X[b][k][p]   (K = 256 fixed)
// MODE 0: + bias[m]   (qkv)
// MODE 1: plain       (gaze pointwise)
// MODE 2: BN epilogue (proj): y = acc*s[m] + (bb[m]-mm[m]*s[m]), s=g/sqrt(v+eps)
// Tiles: BM=64 (M), BN=128 (pixels), BK=16. 256 threads, 8x4 per thread.
// ---------------------------------------------------------------------------
#define GBM 64
#define GBN 128
#define GBK 16
#define WS_PITCH 68  // 64 padded, multiple of 4 for LDS.128

template <int MODE>
__global__ void __launch_bounds__(256) gemm_kernel(
    const float* __restrict__ Wm,  // [M,256] row-major
    const float* __restrict__ X,   // + b*xbs, [256, HW]
    float* __restrict__ Y,         // + b*M*HW
    int M, long long xbs,
    const float* __restrict__ bias,
    const float* __restrict__ bng, const float* __restrict__ bnb,
    const float* __restrict__ bnm, const float* __restrict__ bnv)
{
    __shared__ float Ws[GBK * WS_PITCH];  // [k][m]
    __shared__ float Xs[GBK * GBN];       // [k][p]

    const int tid = threadIdx.x;
    const int tx = tid & 31;   // pixel group (4 px)
    const int ty = tid >> 5;   // m group (8 rows)
    const long long b = blockIdx.z;
    const int m0 = blockIdx.y * GBM;
    const int p0 = blockIdx.x * GBN;
    const float* Xb = X + b * xbs + p0;

    float acc[8][4];
#pragma unroll
    for (int i = 0; i < 8; i++)
#pragma unroll
        for (int j = 0; j < 4; j++) acc[i][j] = 0.f;

    const int wm  = tid >> 2;         // 0..63
    const int wk4 = (tid & 3) << 2;   // 0,4,8,12
    const int xk  = tid >> 5;         // 0..7
    const int xp4 = (tid & 31) << 2;  // 0..124

    for (int k0 = 0; k0 < 256; k0 += GBK) {
        float4 wv = *(const float4*)(Wm + (long long)(m0 + wm) * 256 + k0 + wk4);
        Ws[(wk4 + 0) * WS_PITCH + wm] = wv.x;
        Ws[(wk4 + 1) * WS_PITCH + wm] = wv.y;
        Ws[(wk4 + 2) * WS_PITCH + wm] = wv.z;
        Ws[(wk4 + 3) * WS_PITCH + wm] = wv.w;
        float4 xv0 = *(const float4*)(Xb + (long long)(k0 + xk) * HW_ + xp4);
        float4 xv1 = *(const float4*)(Xb + (long long)(k0 + xk + 8) * HW_ + xp4);
        *(float4*)(Xs + xk * GBN + xp4) = xv0;
        *(float4*)(Xs + (xk + 8) * GBN + xp4) = xv1;
        __syncthreads();
#pragma unroll
        for (int kk = 0; kk < GBK; kk++) {
            float4 xb = *(const float4*)(Xs + kk * GBN + (tx << 2));
            float4 a0 = *(const float4*)(Ws + kk * WS_PITCH + (ty << 3));
            float4 a1 = *(const float4*)(Ws + kk * WS_PITCH + (ty << 3) + 4);
            float av[8] = {a0.x, a0.y, a0.z, a0.w, a1.x, a1.y, a1.z, a1.w};
#pragma unroll
            for (int i = 0; i < 8; i++) {
                acc[i][0] = fmaf(av[i], xb.x, acc[i][0]);
                acc[i][1] = fmaf(av[i], xb.y, acc[i][1]);
                acc[i][2] = fmaf(av[i], xb.z, acc[i][2]);
                acc[i][3] = fmaf(av[i], xb.w, acc[i][3]);
            }
        }
        __syncthreads();
    }

    const long long ybase = b * (long long)M * HW_ + p0 + (tx << 2);
#pragma unroll
    for (int i = 0; i < 8; i++) {
        int m = m0 + (ty << 3) + i;
        float4 r = make_float4(acc[i][0], acc[i][1], acc[i][2], acc[i][3]);
        if (MODE == 0) {
            float bz = __ldg(bias + m);
            r.x += bz; r.y += bz; r.z += bz; r.w += bz;
        } else if (MODE == 2) {
            float s  = __ldg(bng + m) * rsqrtf(__ldg(bnv + m) + 1e-5f);
            float tt = __ldg(bnb + m) - __ldg(bnm + m) * s;
            r.x = fmaf(r.x, s, tt); r.y = fmaf(r.y, s, tt);
            r.z = fmaf(r.z, s, tt); r.w = fmaf(r.w, s, tt);
        }
        *(float4*)(Y + ybase + (long long)m * HW_) = r;
    }
}

// ---------------------------------------------------------------------------
// Window attention. Block = 1 window (4x4 px), 256 threads (warp h = head h).
// qkv layout: [b][o][HW] with o = {q: c, k: 256+c, v: 512+c}.
// smem staged [token][channel] (pitch 260) so global I/O is float4 over pixels
// and compute is float4 over channels.
// ---------------------------------------------------------------------------
#define PITCH 260

__global__ void __launch_bounds__(256) attn_kernel(
    const float* __restrict__ qkv, const float* __restrict__ table,
    float* __restrict__ attn_out)
{
    __shared__ float buf0[16 * PITCH];
    __shared__ float buf1[16 * PITCH];

    const int b = blockIdx.y;
    const int win = blockIdx.x;
    const int wy = win >> 6, wx = win & 63;
    const int tid = threadIdx.x;
    const int c = tid;  // 0..255
    const long long base = (long long)b * 768 * HW_ + (long long)(wy * 4) * W_ + wx * 4;

    // load q -> buf0, k -> buf1
#pragma unroll
    for (int r = 0; r < 4; r++) {
        float4 qv = *(const float4*)(qkv + base + (long long)c * HW_ + r * W_);
        float4 kv = *(const float4*)(qkv + base + (long long)(256 + c) * HW_ + r * W_);
        int t0 = r * 4;
        buf0[(t0 + 0) * PITCH + c] = qv.x; buf0[(t0 + 1) * PITCH + c] = qv.y;
        buf0[(t0 + 2) * PITCH + c] = qv.z; buf0[(t0 + 3) * PITCH + c] = qv.w;
        buf1[(t0 + 0) * PITCH + c] = kv.x; buf1[(t0 + 1) * PITCH + c] = kv.y;
        buf1[(t0 + 2) * PITCH + c] = kv.z; buf1[(t0 + 3) * PITCH + c] = kv.w;
    }
    __syncthreads();

    const int h = tid >> 5;
    const int lane = tid & 31;
    const int t = lane & 15;
    const int dh = lane >> 4;
    const float scale = 0.17677669529663687f;  // 32^-0.5

    float4 qr[8];
#pragma unroll
    for (int i = 0; i < 8; i++)
        qr[i] = *(const float4*)(buf0 + t * PITCH + h * DHEAD_ + i * 4);

    float attn[16];
    float mx = -1e30f;
    const int qi = t >> 2, qj = t & 3;
#pragma unroll
    for (int s = 0; s < 16; s++) {
        float dot = 0.f;
#pragma unroll
        for (int i = 0; i < 8; i++) {
            float4 kr = *(const float4*)(buf1 + s * PITCH + h * DHEAD_ + i * 4);
            dot = fmaf(qr[i].x, kr.x, dot); dot = fmaf(qr[i].y, kr.y, dot);
            dot = fmaf(qr[i].z, kr.z, dot); dot = fmaf(qr[i].w, kr.w, dot);
        }
        int ki = s >> 2, kj = s & 3;
        int idx = (qi - ki + 3) * 7 + (qj - kj + 3);
        attn[s] = fmaf(dot, scale, __ldg(table + idx * 8 + h));
        mx = fmaxf(mx, attn[s]);
    }
    float sum = 0.f;
#pragma unroll
    for (int s = 0; s < 16; s++) { attn[s] = __expf(attn[s] - mx); sum += attn[s]; }
    float inv = 1.f / sum;
#pragma unroll
    for (int s = 0; s < 16; s++) attn[s] *= inv;

    __syncthreads();  // all warps done with q/k
    // load v -> buf0
#pragma unroll
    for (int r = 0; r < 4; r++) {
        float4 vv = *(const float4*)(qkv + base + (long long)(512 + c) * HW_ + r * W_);
        int t0 = r * 4;
        buf0[(t0 + 0) * PITCH + c] = vv.x; buf0[(t0 + 1) * PITCH + c] = vv.y;
        buf0[(t0 + 2) * PITCH + c] = vv.z; buf0[(t0 + 3) * PITCH + c] = vv.w;
    }
    __syncthreads();

    // o-phase: lane (t, dh) computes 16 channels c0 = h*32 + dh*16
    float o[16];
#pragma unroll
    for (int i = 0; i < 16; i++) o[i] = 0.f;
#pragma unroll
    for (int s = 0; s < 16; s++) {
        float a = attn[s];
#pragma unroll
        for (int i = 0; i < 4; i++) {
            float4 vr = *(const float4*)(buf0 + s * PITCH + h * DHEAD_ + dh * 16 + i * 4);
            o[i * 4 + 0] = fmaf(a, vr.x, o[i * 4 + 0]);
            o[i * 4 + 1] = fmaf(a, vr.y, o[i * 4 + 1]);
            o[i * 4 + 2] = fmaf(a, vr.z, o[i * 4 + 2]);
            o[i * 4 + 3] = fmaf(a, vr.w, o[i * 4 + 3]);
        }
    }
    // stage o into buf1 (k no longer needed; disjoint regions per warp)
#pragma unroll
    for (int i = 0; i < 16; i++)
        buf1[t * PITCH + h * DHEAD_ + dh * 16 + i] = o[i];
    __syncthreads();

    // cooperative coalesced write of attn image
    const long long obase = (long long)(b * 256 + c) * HW_ + (long long)(wy * 4) * W_ + wx * 4;
#pragma unroll
    for (int r = 0; r < 4; r++) {
        int t0 = r * 4;
        float4 ov = make_float4(buf1[(t0 + 0) * PITCH + c], buf1[(t0 + 1) * PITCH + c],
                                buf1[(t0 + 2) * PITCH + c], buf1[(t0 + 3) * PITCH + c]);
        *(float4*)(attn_out + obase + r * W_) = ov;
    }
}

// ---------------------------------------------------------------------------
// Fused stencil: pre = ax + ay + v_img + BN(depthwise3x3(vg))
// ax: rows {i-1,i,i+1,i+2}, row 256 -> 254 (reflect), outside [0,256] -> 0, /4
// ay: same over columns. depthwise: zero pad.
// ---------------------------------------------------------------------------
__global__ void __launch_bounds__(256) fuse_kernel(
    const float* __restrict__ attn, const float* __restrict__ qkv,
    const float* __restrict__ vg, const float* __restrict__ dw,
    const float* __restrict__ g, const float* __restrict__ bb,
    const float* __restrict__ mm, const float* __restrict__ vv,
    float* __restrict__ pre)
{
    const int j = blockIdx.x * 32 + threadIdx.x;
    const int i = blockIdx.y * 8 + threadIdx.y;
    const int bc = blockIdx.z;       // b*256 + c
    const int c = bc & 255;
    const int b = bc >> 8;
    const float* A  = attn + (long long)bc * HW_;
    const float* VG = vg + (long long)bc * HW_;
    const float* V  = qkv + (long long)(b * 768 + 512 + c) * HW_;

    float ax = 0.f;
#pragma unroll
    for (int dr = -1; dr <= 2; dr++) {
        int r = i + dr;
        if (r >= 0 && r < 257) {
            if (r == 256) r = 254;
            ax += A[r * W_ + j];
        }
    }
    float ay = 0.f;
#pragma unroll
    for (int dc = -1; dc <= 2; dc++) {
        int cc = j + dc;
        if (cc >= 0 && cc < 257) {
            if (cc == 256) cc = 254;
            ay += A[i * W_ + cc];
        }
    }
    float conv = 0.f;
#pragma unroll
    for (int u = 0; u < 3; u++) {
#pragma unroll
        for (int w = 0; w < 3; w++) {
            int r = i + u - 1, cc = j + w - 1;
            if (r >= 0 && r < H_ && cc >= 0 && cc < W_)
                conv = fmaf(__ldg(dw + c * 9 + u * 3 + w), VG[r * W_ + cc], conv);
        }
    }
    float s = __ldg(g + c) * rsqrtf(__ldg(vv + c) + 1e-5f);
    float res = (ax + ay) * 0.25f + V[i * W_ + j] + fmaf(conv, s, __ldg(bb + c) - __ldg(mm + c) * s);
    pre[(long long)bc * HW_ + i * W_ + j] = res;
}

// ---------------------------------------------------------------------------
extern "C" void kernel_launch(void* const* d_in, const int* in_sizes, int n_in,
                              void* d_out, int out_size)
{
    const float* x        = (const float*)d_in[0];
    const float* qkv_w    = (const float*)d_in[1];
    const float* qkv_b    = (const float*)d_in[2];
    const float* rel_tab  = (const float*)d_in[3];
    const float* gaze_pw  = (const float*)d_in[4];
    const float* gaze_dw  = (const float*)d_in[5];
    const float* gbn_g    = (const float*)d_in[6];
    const float* gbn_b    = (const float*)d_in[7];
    const float* gbn_m    = (const float*)d_in[8];
    const float* gbn_v    = (const float*)d_in[9];
    const float* proj_w   = (const float*)d_in[10];
    const float* pbn_g    = (const float*)d_in[11];
    const float* pbn_b    = (const float*)d_in[12];
    const float* pbn_m    = (const float*)d_in[13];
    const float* pbn_v    = (const float*)d_in[14];
    float* out = (float*)d_out;

    float *qkv, *attn, *vg, *pre;
    cudaGetSymbolAddress((void**)&qkv, d_qkv);
    cudaGetSymbolAddress((void**)&attn, d_attn);
    cudaGetSymbolAddress((void**)&vg, d_vg);
    cudaGetSymbolAddress((void**)&pre, d_pre);

    // 1) qkv = qkv_w @ x + b        [768 x 65536] per batch
    gemm_kernel<0><<<dim3(HW_ / GBN, 768 / GBM, B_), 256>>>(
        qkv_w, x, qkv, 768, (long long)C_ * HW_, qkv_b,
        nullptr, nullptr, nullptr, nullptr);

    // 2) window attention -> attn image
    attn_kernel<<<dim3(4096, B_), 256>>>(qkv, rel_tab, attn);

    // 3) vg = gaze_pw @ v_img  (v_img = qkv slice [512:768])
    gemm_kernel<1><<<dim3(HW_ / GBN, C_ / GBM, B_), 256>>>(
        gaze_pw, qkv + (long long)512 * HW_, vg, C_, (long long)768 * HW_,
        nullptr, nullptr, nullptr, nullptr, nullptr);

    // 4) pre = ax + ay + v + BN(dw3x3(vg))
    fuse_kernel<<<dim3(W_ / 32, H_ / 8, B_ * C_), dim3(32, 8)>>>(
        attn, qkv, vg, gaze_dw, gbn_g, gbn_b, gbn_m, gbn_v, pre);

    // 5) out = BN(proj_w @ pre)   (pad_out + crop around a 1x1 conv is a no-op)
    gemm_kernel<2><<<dim3(HW_ / GBN, C_ / GBM, B_), 256>>>(
        proj_w, pre, out, C_, (long long)C_ * HW_,
        nullptr, pbn_g, pbn_b, pbn_m, pbn_v);
}

// round 2
// speedup vs baseline: 1.0373x; 1.0373x over previous
#include <cuda_runtime.h>
#include <cuda_bf16.h>
#include <mma.h>

using namespace nvcuda;

#define B_   4
#define C_   256
#define H_   256
#define W_   256
#define HW_  65536
#define HEADS_ 8
#define DHEAD_ 32

// Scratch (device globals: allocation-free rule)
__device__ float d_qkv[(long long)B_ * 3 * C_ * HW_];
__device__ float d_attn[(long long)B_ * C_ * HW_];
__device__ float d_vg[(long long)B_ * C_ * HW_];
__device__ float d_pre[(long long)B_ * C_ * HW_];

// ---------------------------------------------------------------------------
// TF32 tensor-core GEMM: Y[b][m][p] = sum_k W[m][k] * X[b][k][p]  (K=256)
// BM=128, BN=128, BK=32. 8 warps (2 M x 4 N), warp tile 64x32 via wmma 16x16x8.
// MODE 0: +bias  MODE 1: plain  MODE 2: BN epilogue
// ---------------------------------------------------------------------------
#define TBM 128
#define TBN 128
#define TBK 32
#define OPITCH 136   // epilogue smem pitch (multiple of 8)

template <int MODE>
__global__ void __launch_bounds__(256) gemm_tc_kernel(
    const float* __restrict__ Wm,  // [M,256] row-major
    const float* __restrict__ X,   // + b*xbs, [256, HW]
    float* __restrict__ Y,         // + b*M*HW
    int M, long long xbs,
    const float* __restrict__ bias,
    const float* __restrict__ bng, const float* __restrict__ bnb,
    const float* __restrict__ bnm, const float* __restrict__ bnv)
{
    // union: mainloop As(128x32)+Bs(32x128) = 8192 floats; epilogue 64x136 = 8704
    __shared__ float sm[8704];
    float* As = sm;          // [128][32]
    float* Bs = sm + 4096;   // [32][128]

    const int tid = threadIdx.x;
    const int warp = tid >> 5;
    const int warp_m = warp >> 2;   // 0..1
    const int warp_n = warp & 3;    // 0..3
    const long long b = blockIdx.z;
    const int m0 = blockIdx.x * TBM;
    const int p0 = blockIdx.y * TBN;
    const float* Xb = X + b * xbs + p0;
    const float* Wb = Wm + (long long)m0 * 256;

    wmma::fragment<wmma::accumulator, 16, 16, 8, float> acc[4][2];
#pragma unroll
    for (int i = 0; i < 4; i++)
#pragma unroll
        for (int j = 0; j < 2; j++) wmma::fill_fragment(acc[i][j], 0.0f);

    // A-load indices: 128 rows x 8 float4; idx = tid + t*256 (t=0..3)
    // B-load indices: 32 rows x 32 float4; row = tid>>5 (+8 each), c4 = tid&31
    const int b_r = tid >> 5;
    const int b_c4 = (tid & 31) << 2;

    for (int k0 = 0; k0 < 256; k0 += TBK) {
#pragma unroll
        for (int t = 0; t < 4; t++) {
            int idx = tid + t * 256;
            int ar = idx >> 3;
            int ac4 = (idx & 7) << 2;
            *(float4*)(As + ar * TBK + ac4) =
                *(const float4*)(Wb + (long long)ar * 256 + k0 + ac4);
        }
#pragma unroll
        for (int t = 0; t < 4; t++) {
            int r = b_r + t * 8;
            *(float4*)(Bs + r * TBN + b_c4) =
                *(const float4*)(Xb + (long long)(k0 + r) * HW_ + b_c4);
        }
        __syncthreads();

#pragma unroll
        for (int ks = 0; ks < 4; ks++) {
            wmma::fragment<wmma::matrix_a, 16, 16, 8, wmma::precision::tf32, wmma::row_major> af[4];
            wmma::fragment<wmma::matrix_b, 16, 16, 8, wmma::precision::tf32, wmma::row_major> bf[2];
#pragma unroll
            for (int i = 0; i < 4; i++) {
                wmma::load_matrix_sync(af[i], As + (warp_m * 64 + i * 16) * TBK + ks * 8, TBK);
#pragma unroll
                for (int e = 0; e < af[i].num_elements; e++)
                    af[i].x[e] = wmma::__float_to_tf32(af[i].x[e]);
            }
#pragma unroll
            for (int j = 0; j < 2; j++) {
                wmma::load_matrix_sync(bf[j], Bs + (ks * 8) * TBN + warp_n * 32 + j * 16, TBN);
#pragma unroll
                for (int e = 0; e < bf[j].num_elements; e++)
                    bf[j].x[e] = wmma::__float_to_tf32(bf[j].x[e]);
            }
#pragma unroll
            for (int i = 0; i < 4; i++)
#pragma unroll
                for (int j = 0; j < 2; j++)
                    wmma::mma_sync(acc[i][j], af[i], bf[j], acc[i][j]);
        }
        __syncthreads();
    }

    // Epilogue in two M-halves through smem (64 x 136)
    const long long ybase = b * (long long)M * HW_ + p0;
#pragma unroll
    for (int wm = 0; wm < 2; wm++) {
        if (warp_m == wm) {
#pragma unroll
            for (int i = 0; i < 4; i++)
#pragma unroll
                for (int j = 0; j < 2; j++)
                    wmma::store_matrix_sync(sm + (i * 16) * OPITCH + warp_n * 32 + j * 16,
                                            acc[i][j], OPITCH, wmma::mem_row_major);
        }
        __syncthreads();
#pragma unroll
        for (int t = 0; t < 8; t++) {
            int idx = tid + t * 256;           // 0..2047
            int row = idx >> 5;                // 0..63
            int c4 = (idx & 31) << 2;          // 0..124
            float4 r = *(float4*)(sm + row * OPITCH + c4);
            int m = m0 + wm * 64 + row;
            if (MODE == 0) {
                float bz = __ldg(bias + m);
                r.x += bz; r.y += bz; r.z += bz; r.w += bz;
            } else if (MODE == 2) {
                float s  = __ldg(bng + m) * rsqrtf(__ldg(bnv + m) + 1e-5f);
                float tt = __ldg(bnb + m) - __ldg(bnm + m) * s;
                r.x = fmaf(r.x, s, tt); r.y = fmaf(r.y, s, tt);
                r.z = fmaf(r.z, s, tt); r.w = fmaf(r.w, s, tt);
            }
            *(float4*)(Y + ybase + (long long)m * HW_ + c4) = r;
        }
        __syncthreads();
    }
}

// ---------------------------------------------------------------------------
// Window attention (unchanged from R0). Block = 1 window, 256 threads.
// ---------------------------------------------------------------------------
#define PITCH 260

__global__ void __launch_bounds__(256) attn_kernel(
    const float* __restrict__ qkv, const float* __restrict__ table,
    float* __restrict__ attn_out)
{
    __shared__ float buf0[16 * PITCH];
    __shared__ float buf1[16 * PITCH];

    const int b = blockIdx.y;
    const int win = blockIdx.x;
    const int wy = win >> 6, wx = win & 63;
    const int tid = threadIdx.x;
    const int c = tid;
    const long long base = (long long)b * 768 * HW_ + (long long)(wy * 4) * W_ + wx * 4;

#pragma unroll
    for (int r = 0; r < 4; r++) {
        float4 qv = *(const float4*)(qkv + base + (long long)c * HW_ + r * W_);
        float4 kv = *(const float4*)(qkv + base + (long long)(256 + c) * HW_ + r * W_);
        int t0 = r * 4;
        buf0[(t0 + 0) * PITCH + c] = qv.x; buf0[(t0 + 1) * PITCH + c] = qv.y;
        buf0[(t0 + 2) * PITCH + c] = qv.z; buf0[(t0 + 3) * PITCH + c] = qv.w;
        buf1[(t0 + 0) * PITCH + c] = kv.x; buf1[(t0 + 1) * PITCH + c] = kv.y;
        buf1[(t0 + 2) * PITCH + c] = kv.z; buf1[(t0 + 3) * PITCH + c] = kv.w;
    }
    __syncthreads();

    const int h = tid >> 5;
    const int lane = tid & 31;
    const int t = lane & 15;
    const int dh = lane >> 4;
    const float scale = 0.17677669529663687f;

    float4 qr[8];
#pragma unroll
    for (int i = 0; i < 8; i++)
        qr[i] = *(const float4*)(buf0 + t * PITCH + h * DHEAD_ + i * 4);

    float attn[16];
    float mx = -1e30f;
    const int qi = t >> 2, qj = t & 3;
#pragma unroll
    for (int s = 0; s < 16; s++) {
        float dot = 0.f;
#pragma unroll
        for (int i = 0; i < 8; i++) {
            float4 kr = *(const float4*)(buf1 + s * PITCH + h * DHEAD_ + i * 4);
            dot = fmaf(qr[i].x, kr.x, dot); dot = fmaf(qr[i].y, kr.y, dot);
            dot = fmaf(qr[i].z, kr.z, dot); dot = fmaf(qr[i].w, kr.w, dot);
        }
        int ki = s >> 2, kj = s & 3;
        int idx = (qi - ki + 3) * 7 + (qj - kj + 3);
        attn[s] = fmaf(dot, scale, __ldg(table + idx * 8 + h));
        mx = fmaxf(mx, attn[s]);
    }
    float sum = 0.f;
#pragma unroll
    for (int s = 0; s < 16; s++) { attn[s] = __expf(attn[s] - mx); sum += attn[s]; }
    float inv = 1.f / sum;
#pragma unroll
    for (int s = 0; s < 16; s++) attn[s] *= inv;

    __syncthreads();
#pragma unroll
    for (int r = 0; r < 4; r++) {
        float4 vv = *(const float4*)(qkv + base + (long long)(512 + c) * HW_ + r * W_);
        int t0 = r * 4;
        buf0[(t0 + 0) * PITCH + c] = vv.x; buf0[(t0 + 1) * PITCH + c] = vv.y;
        buf0[(t0 + 2) * PITCH + c] = vv.z; buf0[(t0 + 3) * PITCH + c] = vv.w;
    }
    __syncthreads();

    float o[16];
#pragma unroll
    for (int i = 0; i < 16; i++) o[i] = 0.f;
#pragma unroll
    for (int s = 0; s < 16; s++) {
        float a = attn[s];
#pragma unroll
        for (int i = 0; i < 4; i++) {
            float4 vr = *(const float4*)(buf0 + s * PITCH + h * DHEAD_ + dh * 16 + i * 4);
            o[i * 4 + 0] = fmaf(a, vr.x, o[i * 4 + 0]);
            o[i * 4 + 1] = fmaf(a, vr.y, o[i * 4 + 1]);
            o[i * 4 + 2] = fmaf(a, vr.z, o[i * 4 + 2]);
            o[i * 4 + 3] = fmaf(a, vr.w, o[i * 4 + 3]);
        }
    }
#pragma unroll
    for (int i = 0; i < 16; i++)
        buf1[t * PITCH + h * DHEAD_ + dh * 16 + i] = o[i];
    __syncthreads();

    const long long obase = (long long)(b * 256 + c) * HW_ + (long long)(wy * 4) * W_ + wx * 4;
#pragma unroll
    for (int r = 0; r < 4; r++) {
        int t0 = r * 4;
        float4 ov = make_float4(buf1[(t0 + 0) * PITCH + c], buf1[(t0 + 1) * PITCH + c],
                                buf1[(t0 + 2) * PITCH + c], buf1[(t0 + 3) * PITCH + c]);
        *(float4*)(attn_out + obase + r * W_) = ov;
    }
}

// ---------------------------------------------------------------------------
// Fused stencil (vectorized): each thread -> float4 of outputs at (i, j0..j0+3)
// pre = (ax+ay)/4 + v + BN(dw3x3(vg))
// ---------------------------------------------------------------------------
__global__ void __launch_bounds__(256) fuse_kernel(
    const float* __restrict__ attn, const float* __restrict__ qkv,
    const float* __restrict__ vg, const float* __restrict__ dw,
    const float* __restrict__ g, const float* __restrict__ bb,
    const float* __restrict__ mm, const float* __restrict__ vv,
    float* __restrict__ pre)
{
    const int j0 = threadIdx.x << 2;                       // 0..252
    const int i  = blockIdx.y * 4 + threadIdx.y;           // row
    const int bc = blockIdx.z;
    const int c = bc & 255;
    const int b = bc >> 8;
    const float* A  = attn + (long long)bc * HW_;
    const float* VG = vg + (long long)bc * HW_;
    const float* V  = qkv + (long long)(b * 768 + 512 + c) * HW_;

    // ax: rows i-1,i,i+1,i+2 (reflect 256->254, outside->0)
    float4 ax = make_float4(0.f, 0.f, 0.f, 0.f);
    float4 rowi;
#pragma unroll
    for (int dr = -1; dr <= 2; dr++) {
        int r = i + dr;
        bool valid = (r >= 0 && r < 257);
        if (r == 256) r = 254;
        if (valid) {
            float4 t = *(const float4*)(A + r * W_ + j0);
            ax.x += t.x; ax.y += t.y; ax.z += t.z; ax.w += t.w;
            if (dr == 0) rowi = t;
        }
    }

    // ay: needs cols j0-1 .. j0+5 of row i
    float c7[7];
    c7[0] = (j0 > 0) ? A[i * W_ + j0 - 1] : 0.f;
    c7[1] = rowi.x; c7[2] = rowi.y; c7[3] = rowi.z; c7[4] = rowi.w;
    if (j0 < 252) {
        float2 rr = *(const float2*)(A + i * W_ + j0 + 4);
        c7[5] = rr.x; c7[6] = rr.y;
    } else {             // j0 == 252: col 256 reflects to 254 (= rowi.z), col 257 excluded
        c7[5] = rowi.z; c7[6] = 0.f;
    }
    float4 ay;
    ay.x = c7[0] + c7[1] + c7[2] + c7[3];
    ay.y = c7[1] + c7[2] + c7[3] + c7[4];
    ay.z = c7[2] + c7[3] + c7[4] + c7[5];
    ay.w = c7[3] + c7[4] + c7[5] + c7[6];

    // depthwise 3x3 on vg (zero pad)
    float cv[4] = {0.f, 0.f, 0.f, 0.f};
#pragma unroll
    for (int dr = -1; dr <= 1; dr++) {
        int r = i + dr;
        if (r < 0 || r >= H_) continue;
        float w0 = __ldg(dw + c * 9 + (dr + 1) * 3 + 0);
        float w1 = __ldg(dw + c * 9 + (dr + 1) * 3 + 1);
        float w2 = __ldg(dw + c * 9 + (dr + 1) * 3 + 2);
        float cc[6];
        cc[0] = (j0 > 0) ? VG[r * W_ + j0 - 1] : 0.f;
        float4 ctr = *(const float4*)(VG + r * W_ + j0);
        cc[1] = ctr.x; cc[2] = ctr.y; cc[3] = ctr.z; cc[4] = ctr.w;
        cc[5] = (j0 < 252) ? VG[r * W_ + j0 + 4] : 0.f;
#pragma unroll
        for (int l = 0; l < 4; l++)
            cv[l] = fmaf(w0, cc[l], fmaf(w1, cc[l + 1], fmaf(w2, cc[l + 2], cv[l])));
    }

    float4 v4 = *(const float4*)(V + i * W_ + j0);
    float s  = __ldg(g + c) * rsqrtf(__ldg(vv + c) + 1e-5f);
    float tt = __ldg(bb + c) - __ldg(mm + c) * s;

    float4 res;
    res.x = (ax.x + ay.x) * 0.25f + v4.x + fmaf(cv[0], s, tt);
    res.y = (ax.y + ay.y) * 0.25f + v4.y + fmaf(cv[1], s, tt);
    res.z = (ax.z + ay.z) * 0.25f + v4.z + fmaf(cv[2], s, tt);
    res.w = (ax.w + ay.w) * 0.25f + v4.w + fmaf(cv[3], s, tt);
    *(float4*)(pre + (long long)bc * HW_ + i * W_ + j0) = res;
}

// ---------------------------------------------------------------------------
extern "C" void kernel_launch(void* const* d_in, const int* in_sizes, int n_in,
                              void* d_out, int out_size)
{
    const float* x        = (const float*)d_in[0];
    const float* qkv_w    = (const float*)d_in[1];
    const float* qkv_b    = (const float*)d_in[2];
    const float* rel_tab  = (const float*)d_in[3];
    const float* gaze_pw  = (const float*)d_in[4];
    const float* gaze_dw  = (const float*)d_in[5];
    const float* gbn_g    = (const float*)d_in[6];
    const float* gbn_b    = (const float*)d_in[7];
    const float* gbn_m    = (const float*)d_in[8];
    const float* gbn_v    = (const float*)d_in[9];
    const float* proj_w   = (const float*)d_in[10];
    const float* pbn_g    = (const float*)d_in[11];
    const float* pbn_b    = (const float*)d_in[12];
    const float* pbn_m    = (const float*)d_in[13];
    const float* pbn_v    = (const float*)d_in[14];
    float* out = (float*)d_out;

    float *qkv, *attn, *vg, *pre;
    cudaGetSymbolAddress((void**)&qkv, d_qkv);
    cudaGetSymbolAddress((void**)&attn, d_attn);
    cudaGetSymbolAddress((void**)&vg, d_vg);
    cudaGetSymbolAddress((void**)&pre, d_pre);

    // 1) qkv = qkv_w @ x + b   (grid.x = M tiles so X panel stays L2-resident)
    gemm_tc_kernel<0><<<dim3(768 / TBM, HW_ / TBN, B_), 256>>>(
        qkv_w, x, qkv, 768, (long long)C_ * HW_, qkv_b,
        nullptr, nullptr, nullptr, nullptr);

    // 2) window attention
    attn_kernel<<<dim3(4096, B_), 256>>>(qkv, rel_tab, attn);

    // 3) vg = gaze_pw @ v_img
    gemm_tc_kernel<1><<<dim3(C_ / TBM, HW_ / TBN, B_), 256>>>(
        gaze_pw, qkv + (long long)512 * HW_, vg, C_, (long long)768 * HW_,
        nullptr, nullptr, nullptr, nullptr, nullptr);

    // 4) pre = (ax+ay)/4 + v + BN(dw3x3(vg))
    fuse_kernel<<<dim3(1, H_ / 4, B_ * C_), dim3(64, 4)>>>(
        attn, qkv, vg, gaze_dw, gbn_g, gbn_b, gbn_m, gbn_v, pre);

    // 5) out = BN(proj_w @ pre)
    gemm_tc_kernel<2><<<dim3(C_ / TBM, HW_ / TBN, B_), 256>>>(
        proj_w, pre, out, C_, (long long)C_ * HW_,
        nullptr, pbn_g, pbn_b, pbn_m, pbn_v);
}

// round 4
// speedup vs baseline: 3.0057x; 2.8977x over previous
#include <cuda_runtime.h>
#include <cuda_fp16.h>
#include <cstdint>

#define B_   4
#define C_   256
#define H_   256
#define W_   256
#define HW_  65536
#define DHEAD_ 32

// Scratch (device globals: allocation-free rule)
__device__ float  d_qkv[(long long)B_ * 3 * C_ * HW_];   // fp32, attn/fuse consumers
__device__ float  d_attn[(long long)B_ * C_ * HW_];
__device__ float  d_vg[(long long)B_ * C_ * HW_];
__device__ __half d_xh[(long long)B_ * C_ * HW_];        // x in fp16
__device__ __half d_vh[(long long)B_ * C_ * HW_];        // v slice in fp16 (gaze input)
__device__ __half d_preh[(long long)B_ * C_ * HW_];      // pre in fp16 (proj input)
__device__ __half d_wtq[768 * 256];                      // qkv_w^T  [k][m]
__device__ __half d_wtg[256 * 256];                      // gaze_pw^T
__device__ __half d_wtp[256 * 256];                      // proj_w^T

// ---------------------------------------------------------------------------
// PTX helpers (all sm_80-baseline: legal on compute_103 target)
// ---------------------------------------------------------------------------
__device__ __forceinline__ uint32_t smem_u32(const void* p) {
    uint32_t a;
    asm("{ .reg .u64 t; cvta.to.shared.u64 t, %1; cvt.u32.u64 %0, t; }" : "=r"(a) : "l"(p));
    return a;
}
__device__ __forceinline__ void cp16(uint32_t s, const void* g) {
    asm volatile("cp.async.cg.shared.global [%0], [%1], 16;" :: "r"(s), "l"(g));
}
#define CP_COMMIT() asm volatile("cp.async.commit_group;" ::: "memory")
#define CP_WAIT(N)  asm volatile("cp.async.wait_group %0;" :: "n"(N) : "memory")

__device__ __forceinline__ void ldsm4t(uint32_t* r, uint32_t a) {
    asm volatile("ldmatrix.sync.aligned.m8n8.x4.trans.shared.b16 {%0,%1,%2,%3}, [%4];"
                 : "=r"(r[0]), "=r"(r[1]), "=r"(r[2]), "=r"(r[3]) : "r"(a));
}
__device__ __forceinline__ void mma16816(float* d, const uint32_t* a, uint32_t b0, uint32_t b1) {
    asm volatile(
        "mma.sync.aligned.m16n8k16.row.col.f32.f16.f16.f32 "
        "{%0,%1,%2,%3}, {%4,%5,%6,%7}, {%8,%9}, {%0,%1,%2,%3};"
        : "+f"(d[0]), "+f"(d[1]), "+f"(d[2]), "+f"(d[3])
        : "r"(a[0]), "r"(a[1]), "r"(a[2]), "r"(a[3]), "r"(b0), "r"(b1));
}

// ---------------------------------------------------------------------------
// Pre-pass: fp32 -> fp16 image convert ; weight transpose+convert W[m][k]->Wt[k][m]
// ---------------------------------------------------------------------------
__global__ void __launch_bounds__(256) conv_x_kernel(const float* __restrict__ x,
                                                     __half* __restrict__ xh, long long n4) {
    long long i = ((long long)blockIdx.x * 256 + threadIdx.x);
    if (i >= n4) return;
    float4 v = *(const float4*)(x + i * 4);
    __half2* o = (__half2*)(xh + i * 4);
    o[0] = __floats2half2_rn(v.x, v.y);
    o[1] = __floats2half2_rn(v.z, v.w);
}

__global__ void __launch_bounds__(256) transw_kernel(const float* __restrict__ w,
                                                     __half* __restrict__ wt, int M) {
    int i = blockIdx.x * 256 + threadIdx.x;   // i = k*M + m
    if (i >= 256 * M) return;
    int k = i / M, m = i - k * M;
    wt[i] = __float2half_rn(w[m * 256 + k]);
}

// ---------------------------------------------------------------------------
// fp16 HMMA GEMM: Y[b][m][p] = sum_k Wt[k][m] * X[b][k][p]
// CTA: 128m x 128p, K=256 in 8 chunks of 32, cp.async double-buffered.
// Both tiles K-major [k][col] fp16, 256B rows, XOR-swizzled 16B segments,
// fragments via ldmatrix.x4.trans. 8 warps = 4 m-warps x 2 p-warps.
// MODE 0: +bias (AUXV: also emit fp16 copy of m>=512 rows)  MODE 1: plain
// MODE 2: BN epilogue
// ---------------------------------------------------------------------------
template <int MODE, bool AUXV>
__global__ void __launch_bounds__(256, 2) gemm_h_kernel(
    const __half* __restrict__ Wt,   // [256][Mtot]
    const __half* __restrict__ X,    // + b*xbs, [256][HW] fp16
    float* __restrict__ Y,           // [b][Mtot][HW] fp32
    __half* __restrict__ vaux,       // fp16 aux (qkv v slice) or null
    int Mtot, long long xbs,
    const float* __restrict__ bias,
    const float* __restrict__ bng, const float* __restrict__ bnb,
    const float* __restrict__ bnm, const float* __restrict__ bnv)
{
    __shared__ __align__(16) char smem[2][16384];  // [buf][Wtile 8KB | Xtile 8KB]

    const int tid = threadIdx.x;
    const int warp = tid >> 5;
    const int lane = tid & 31;
    const int wm = warp >> 1;          // 0..3
    const int wp = warp & 1;           // 0..1
    const long long b = blockIdx.z;
    const int mbase = blockIdx.x * 128;
    const int p0 = blockIdx.y * 128;
    const __half* Wg = Wt + mbase;             // row k: + k*Mtot
    const __half* Xg = X + b * xbs + p0;       // row k: + k*HW

    const uint32_t sb = smem_u32(smem);

    float acc[2][8][4];
#pragma unroll
    for (int i = 0; i < 2; i++)
#pragma unroll
        for (int j = 0; j < 8; j++)
#pragma unroll
            for (int l = 0; l < 4; l++) acc[i][j][l] = 0.f;

    // stage chunk c into buf (1024 x 16B, 4 per thread)
    auto stage = [&](int c) {
        const int k0 = c * 32;
        const uint32_t base = sb + (uint32_t)(c & 1) * 16384;
#pragma unroll
        for (int q = 0; q < 4; q++) {
            int sid = tid + q * 256;
            int tile = sid >> 9, rem = sid & 511;
            int kr = rem >> 4, s = rem & 15;
            uint32_t sa = base + (uint32_t)tile * 8192 + (uint32_t)kr * 256
                        + (uint32_t)((s ^ (kr & 7)) << 4);
            const __half* g = (tile == 0)
                ? Wg + (long long)(k0 + kr) * Mtot + s * 8
                : Xg + (long long)(k0 + kr) * HW_ + s * 8;
            cp16(sa, g);
        }
        CP_COMMIT();
    };

    stage(0);
    stage(1);

#pragma unroll 1
    for (int c = 0; c < 8; c++) {
        if (c < 7) { CP_WAIT(1); } else { CP_WAIT(0); }
        __syncthreads();
        const uint32_t wtile = sb + (uint32_t)(c & 1) * 16384;
        const uint32_t xtile = wtile + 8192;
#pragma unroll
        for (int ks = 0; ks < 2; ks++) {
            const int kb = ks * 16;
            // frag address: lane-dependent row/col within [k][col] swizzled tile
            auto faddr = [&](uint32_t tbase, int col0) -> uint32_t {
                int kr = kb + ((lane >> 4) & 1) * 8 + (lane & 7);
                int seg = (col0 >> 3) + ((lane >> 3) & 1);
                return tbase + (uint32_t)kr * 256 + (uint32_t)(((seg ^ (kr & 7)) & 15) << 4);
            };
            uint32_t A[2][4];
            ldsm4t(A[0], faddr(wtile, wm * 32));
            ldsm4t(A[1], faddr(wtile, wm * 32 + 16));
            uint32_t Bf[4][4];
#pragma unroll
            for (int bi = 0; bi < 4; bi++)
                ldsm4t(Bf[bi], faddr(xtile, wp * 64 + bi * 16));
#pragma unroll
            for (int mf = 0; mf < 2; mf++)
#pragma unroll
                for (int nf = 0; nf < 8; nf++)
                    mma16816(acc[mf][nf], A[mf], Bf[nf >> 1][nf & 1], Bf[nf >> 1][(nf & 1) + 2]);
        }
        __syncthreads();
        if (c + 2 < 8) stage(c + 2);
    }

    // ---- epilogue: direct stores (float2 per frag-row) ----
    const int gr = lane >> 2, tg = lane & 3;
    const long long ybase = b * (long long)Mtot * HW_;
#pragma unroll
    for (int mf = 0; mf < 2; mf++) {
        const int m0 = mbase + wm * 32 + mf * 16 + gr;   // and m0+8
        float s0 = 0.f, t0 = 0.f, s1 = 0.f, t1 = 0.f;
        if (MODE == 0) {
            t0 = __ldg(bias + m0); t1 = __ldg(bias + m0 + 8);
        } else if (MODE == 2) {
            s0 = __ldg(bng + m0) * rsqrtf(__ldg(bnv + m0) + 1e-5f);
            t0 = __ldg(bnb + m0) - __ldg(bnm + m0) * s0;
            s1 = __ldg(bng + m0 + 8) * rsqrtf(__ldg(bnv + m0 + 8) + 1e-5f);
            t1 = __ldg(bnb + m0 + 8) - __ldg(bnm + m0 + 8) * s1;
        }
#pragma unroll
        for (int nf = 0; nf < 8; nf++) {
            const int p = p0 + wp * 64 + nf * 8 + tg * 2;
            float2 v0 = make_float2(acc[mf][nf][0], acc[mf][nf][1]);
            float2 v1 = make_float2(acc[mf][nf][2], acc[mf][nf][3]);
            if (MODE == 0) {
                v0.x += t0; v0.y += t0; v1.x += t1; v1.y += t1;
            } else if (MODE == 2) {
                v0.x = fmaf(v0.x, s0, t0); v0.y = fmaf(v0.y, s0, t0);
                v1.x = fmaf(v1.x, s1, t1); v1.y = fmaf(v1.y, s1, t1);
            }
            *(float2*)(Y + ybase + (long long)m0 * HW_ + p) = v0;
            *(float2*)(Y + ybase + (long long)(m0 + 8) * HW_ + p) = v1;
            if (AUXV) {
                if (m0 >= 512) {
                    *(__half2*)(vaux + ((long long)(b * 256 + m0 - 512)) * HW_ + p) =
                        __floats2half2_rn(v0.x, v0.y);
                    *(__half2*)(vaux + ((long long)(b * 256 + m0 - 504)) * HW_ + p) =
                        __floats2half2_rn(v1.x, v1.y);
                }
            }
        }
    }
}

// ---------------------------------------------------------------------------
// Window attention (fp32, unchanged). Block = 1 window, 256 threads.
// ---------------------------------------------------------------------------
#define PITCH 260

__global__ void __launch_bounds__(256) attn_kernel(
    const float* __restrict__ qkv, const float* __restrict__ table,
    float* __restrict__ attn_out)
{
    __shared__ float buf0[16 * PITCH];
    __shared__ float buf1[16 * PITCH];

    const int b = blockIdx.y;
    const int win = blockIdx.x;
    const int wy = win >> 6, wx = win & 63;
    const int tid = threadIdx.x;
    const int c = tid;
    const long long base = (long long)b * 768 * HW_ + (long long)(wy * 4) * W_ + wx * 4;

#pragma unroll
    for (int r = 0; r < 4; r++) {
        float4 qv = *(const float4*)(qkv + base + (long long)c * HW_ + r * W_);
        float4 kv = *(const float4*)(qkv + base + (long long)(256 + c) * HW_ + r * W_);
        int t0 = r * 4;
        buf0[(t0 + 0) * PITCH + c] = qv.x; buf0[(t0 + 1) * PITCH + c] = qv.y;
        buf0[(t0 + 2) * PITCH + c] = qv.z; buf0[(t0 + 3) * PITCH + c] = qv.w;
        buf1[(t0 + 0) * PITCH + c] = kv.x; buf1[(t0 + 1) * PITCH + c] = kv.y;
        buf1[(t0 + 2) * PITCH + c] = kv.z; buf1[(t0 + 3) * PITCH + c] = kv.w;
    }
    __syncthreads();

    const int h = tid >> 5;
    const int lane = tid & 31;
    const int t = lane & 15;
    const int dh = lane >> 4;
    const float scale = 0.17677669529663687f;

    float4 qr[8];
#pragma unroll
    for (int i = 0; i < 8; i++)
        qr[i] = *(const float4*)(buf0 + t * PITCH + h * DHEAD_ + i * 4);

    float attn[16];
    float mx = -1e30f;
    const int qi = t >> 2, qj = t & 3;
#pragma unroll
    for (int s = 0; s < 16; s++) {
        float dot = 0.f;
#pragma unroll
        for (int i = 0; i < 8; i++) {
            float4 kr = *(const float4*)(buf1 + s * PITCH + h * DHEAD_ + i * 4);
            dot = fmaf(qr[i].x, kr.x, dot); dot = fmaf(qr[i].y, kr.y, dot);
            dot = fmaf(qr[i].z, kr.z, dot); dot = fmaf(qr[i].w, kr.w, dot);
        }
        int ki = s >> 2, kj = s & 3;
        int idx = (qi - ki + 3) * 7 + (qj - kj + 3);
        attn[s] = fmaf(dot, scale, __ldg(table + idx * 8 + h));
        mx = fmaxf(mx, attn[s]);
    }
    float sum = 0.f;
#pragma unroll
    for (int s = 0; s < 16; s++) { attn[s] = __expf(attn[s] - mx); sum += attn[s]; }
    float inv = 1.f / sum;
#pragma unroll
    for (int s = 0; s < 16; s++) attn[s] *= inv;

    __syncthreads();
#pragma unroll
    for (int r = 0; r < 4; r++) {
        float4 vv = *(const float4*)(qkv + base + (long long)(512 + c) * HW_ + r * W_);
        int t0 = r * 4;
        buf0[(t0 + 0) * PITCH + c] = vv.x; buf0[(t0 + 1) * PITCH + c] = vv.y;
        buf0[(t0 + 2) * PITCH + c] = vv.z; buf0[(t0 + 3) * PITCH + c] = vv.w;
    }
    __syncthreads();

    float o[16];
#pragma unroll
    for (int i = 0; i < 16; i++) o[i] = 0.f;
#pragma unroll
    for (int s = 0; s < 16; s++) {
        float a = attn[s];
#pragma unroll
        for (int i = 0; i < 4; i++) {
            float4 vr = *(const float4*)(buf0 + s * PITCH + h * DHEAD_ + dh * 16 + i * 4);
            o[i * 4 + 0] = fmaf(a, vr.x, o[i * 4 + 0]);
            o[i * 4 + 1] = fmaf(a, vr.y, o[i * 4 + 1]);
            o[i * 4 + 2] = fmaf(a, vr.z, o[i * 4 + 2]);
            o[i * 4 + 3] = fmaf(a, vr.w, o[i * 4 + 3]);
        }
    }
#pragma unroll
    for (int i = 0; i < 16; i++)
        buf1[t * PITCH + h * DHEAD_ + dh * 16 + i] = o[i];
    __syncthreads();

    const long long obase = (long long)(b * 256 + c) * HW_ + (long long)(wy * 4) * W_ + wx * 4;
#pragma unroll
    for (int r = 0; r < 4; r++) {
        int t0 = r * 4;
        float4 ov = make_float4(buf1[(t0 + 0) * PITCH + c], buf1[(t0 + 1) * PITCH + c],
                                buf1[(t0 + 2) * PITCH + c], buf1[(t0 + 3) * PITCH + c]);
        *(float4*)(attn_out + obase + r * W_) = ov;
    }
}

// ---------------------------------------------------------------------------
// Fused stencil: pre(fp16) = (ax+ay)/4 + v + BN(dw3x3(vg))
// ---------------------------------------------------------------------------
__global__ void __launch_bounds__(256) fuse_kernel(
    const float* __restrict__ attn, const float* __restrict__ qkv,
    const float* __restrict__ vg, const float* __restrict__ dw,
    const float* __restrict__ g, const float* __restrict__ bb,
    const float* __restrict__ mm, const float* __restrict__ vv,
    __half* __restrict__ pre)
{
    const int j0 = threadIdx.x << 2;
    const int i  = blockIdx.y * 4 + threadIdx.y;
    const int bc = blockIdx.z;
    const int c = bc & 255;
    const int b = bc >> 8;
    const float* A  = attn + (long long)bc * HW_;
    const float* VG = vg + (long long)bc * HW_;
    const float* V  = qkv + (long long)(b * 768 + 512 + c) * HW_;

    float4 ax = make_float4(0.f, 0.f, 0.f, 0.f);
    float4 rowi;
#pragma unroll
    for (int dr = -1; dr <= 2; dr++) {
        int r = i + dr;
        bool valid = (r >= 0 && r < 257);
        if (r == 256) r = 254;
        if (valid) {
            float4 t = *(const float4*)(A + r * W_ + j0);
            ax.x += t.x; ax.y += t.y; ax.z += t.z; ax.w += t.w;
            if (dr == 0) rowi = t;
        }
    }

    float c7[7];
    c7[0] = (j0 > 0) ? A[i * W_ + j0 - 1] : 0.f;
    c7[1] = rowi.x; c7[2] = rowi.y; c7[3] = rowi.z; c7[4] = rowi.w;
    if (j0 < 252) {
        float2 rr = *(const float2*)(A + i * W_ + j0 + 4);
        c7[5] = rr.x; c7[6] = rr.y;
    } else {
        c7[5] = rowi.z; c7[6] = 0.f;
    }
    float4 ay;
    ay.x = c7[0] + c7[1] + c7[2] + c7[3];
    ay.y = c7[1] + c7[2] + c7[3] + c7[4];
    ay.z = c7[2] + c7[3] + c7[4] + c7[5];
    ay.w = c7[3] + c7[4] + c7[5] + c7[6];

    float cv[4] = {0.f, 0.f, 0.f, 0.f};
#pragma unroll
    for (int dr = -1; dr <= 1; dr++) {
        int r = i + dr;
        if (r < 0 || r >= H_) continue;
        float w0 = __ldg(dw + c * 9 + (dr + 1) * 3 + 0);
        float w1 = __ldg(dw + c * 9 + (dr + 1) * 3 + 1);
        float w2 = __ldg(dw + c * 9 + (dr + 1) * 3 + 2);
        float cc[6];
        cc[0] = (j0 > 0) ? VG[r * W_ + j0 - 1] : 0.f;
        float4 ctr = *(const float4*)(VG + r * W_ + j0);
        cc[1] = ctr.x; cc[2] = ctr.y; cc[3] = ctr.z; cc[4] = ctr.w;
        cc[5] = (j0 < 252) ? VG[r * W_ + j0 + 4] : 0.f;
#pragma unroll
        for (int l = 0; l < 4; l++)
            cv[l] = fmaf(w0, cc[l], fmaf(w1, cc[l + 1], fmaf(w2, cc[l + 2], cv[l])));
    }

    float4 v4 = *(const float4*)(V + i * W_ + j0);
    float s  = __ldg(g + c) * rsqrtf(__ldg(vv + c) + 1e-5f);
    float tt = __ldg(bb + c) - __ldg(mm + c) * s;

    float rx = (ax.x + ay.x) * 0.25f + v4.x + fmaf(cv[0], s, tt);
    float ry = (ax.y + ay.y) * 0.25f + v4.y + fmaf(cv[1], s, tt);
    float rz = (ax.z + ay.z) * 0.25f + v4.z + fmaf(cv[2], s, tt);
    float rw = (ax.w + ay.w) * 0.25f + v4.w + fmaf(cv[3], s, tt);
    __half2* o = (__half2*)(pre + (long long)bc * HW_ + i * W_ + j0);
    o[0] = __floats2half2_rn(rx, ry);
    o[1] = __floats2half2_rn(rz, rw);
}

// ---------------------------------------------------------------------------
extern "C" void kernel_launch(void* const* d_in, const int* in_sizes, int n_in,
                              void* d_out, int out_size)
{
    const float* x        = (const float*)d_in[0];
    const float* qkv_w    = (const float*)d_in[1];
    const float* qkv_b    = (const float*)d_in[2];
    const float* rel_tab  = (const float*)d_in[3];
    const float* gaze_pw  = (const float*)d_in[4];
    const float* gaze_dw  = (const float*)d_in[5];
    const float* gbn_g    = (const float*)d_in[6];
    const float* gbn_b    = (const float*)d_in[7];
    const float* gbn_m    = (const float*)d_in[8];
    const float* gbn_v    = (const float*)d_in[9];
    const float* proj_w   = (const float*)d_in[10];
    const float* pbn_g    = (const float*)d_in[11];
    const float* pbn_b    = (const float*)d_in[12];
    const float* pbn_m    = (const float*)d_in[13];
    const float* pbn_v    = (const float*)d_in[14];
    float* out = (float*)d_out;

    float *qkv, *attn, *vg;
    __half *xh, *vh, *preh, *wtq, *wtg, *wtp;
    cudaGetSymbolAddress((void**)&qkv, d_qkv);
    cudaGetSymbolAddress((void**)&attn, d_attn);
    cudaGetSymbolAddress((void**)&vg, d_vg);
    cudaGetSymbolAddress((void**)&xh, d_xh);
    cudaGetSymbolAddress((void**)&vh, d_vh);
    cudaGetSymbolAddress((void**)&preh, d_preh);
    cudaGetSymbolAddress((void**)&wtq, d_wtq);
    cudaGetSymbolAddress((void**)&wtg, d_wtg);
    cudaGetSymbolAddress((void**)&wtp, d_wtp);

    // 0) pre-pass: x -> fp16 ; weights -> transposed fp16 [k][m]
    conv_x_kernel<<<(int)(((long long)B_ * C_ * HW_ / 4 + 255) / 256), 256>>>(
        x, xh, (long long)B_ * C_ * HW_ / 4);
    transw_kernel<<<(256 * 768 + 255) / 256, 256>>>(qkv_w, wtq, 768);
    transw_kernel<<<(256 * 256 + 255) / 256, 256>>>(gaze_pw, wtg, 256);
    transw_kernel<<<(256 * 256 + 255) / 256, 256>>>(proj_w, wtp, 256);

    // 1) qkv = qkv_w @ x + b (fp32 out; fp16 aux copy of v slice)
    gemm_h_kernel<0, true><<<dim3(768 / 128, HW_ / 128, B_), 256>>>(
        wtq, xh, qkv, vh, 768, (long long)C_ * HW_,
        qkv_b, nullptr, nullptr, nullptr, nullptr);

    // 2) window attention (fp32)
    attn_kernel<<<dim3(4096, B_), 256>>>(qkv, rel_tab, attn);

    // 3) vg = gaze_pw @ v  (fp16 in, fp32 out)
    gemm_h_kernel<1, false><<<dim3(256 / 128, HW_ / 128, B_), 256>>>(
        wtg, vh, vg, nullptr, 256, (long long)C_ * HW_,
        nullptr, nullptr, nullptr, nullptr, nullptr);

    // 4) pre(fp16) = (ax+ay)/4 + v + BN(dw3x3(vg))
    fuse_kernel<<<dim3(1, H_ / 4, B_ * C_), dim3(64, 4)>>>(
        attn, qkv, vg, gaze_dw, gbn_g, gbn_b, gbn_m, gbn_v, preh);

    // 5) out = BN(proj_w @ pre)
    gemm_h_kernel<2, false><<<dim3(256 / 128, HW_ / 128, B_), 256>>>(
        wtp, preh, out, nullptr, 256, (long long)C_ * HW_,
        nullptr, pbn_g, pbn_b, pbn_m, pbn_v);
}

// round 5
// speedup vs baseline: 3.1252x; 1.0397x over previous
#include <cuda_runtime.h>
#include <cuda_fp16.h>
#include <cstdint>

#define B_   4
#define C_   256
#define H_   256
#define W_   256
#define HW_  65536
#define DHEAD_ 32

// Scratch (device globals; uint4 for 16B alignment)
__device__ uint4 d_qkvh_[(long long)B_ * 768 * HW_ / 8];   // fp16 qkv  (403 MB)
__device__ uint4 d_attnh_[(long long)B_ * C_ * HW_ / 8];   // fp16 attn (134 MB)
__device__ uint4 d_vgh_[(long long)B_ * C_ * HW_ / 8];     // fp16 vg
__device__ uint4 d_preh_[(long long)B_ * C_ * HW_ / 8];    // fp16 pre
__device__ uint4 d_xh_[(long long)B_ * C_ * HW_ / 8];      // fp16 x
__device__ uint4 d_wtq_[768 * 256 / 8];                    // qkv_w^T fp16 [k][m]
__device__ uint4 d_wtg_[256 * 256 / 8];
__device__ uint4 d_wtp_[256 * 256 / 8];

// ---------------------------------------------------------------------------
__device__ __forceinline__ uint32_t smem_u32(const void* p) {
    uint32_t a;
    asm("{ .reg .u64 t; cvta.to.shared.u64 t, %1; cvt.u32.u64 %0, t; }" : "=r"(a) : "l"(p));
    return a;
}
__device__ __forceinline__ void cp16(uint32_t s, const void* g) {
    asm volatile("cp.async.cg.shared.global [%0], [%1], 16;" :: "r"(s), "l"(g));
}
#define CP_COMMIT() asm volatile("cp.async.commit_group;" ::: "memory")
#define CP_WAIT(N)  asm volatile("cp.async.wait_group %0;" :: "n"(N) : "memory")

__device__ __forceinline__ void ldsm4t(uint32_t* r, uint32_t a) {
    asm volatile("ldmatrix.sync.aligned.m8n8.x4.trans.shared.b16 {%0,%1,%2,%3}, [%4];"
                 : "=r"(r[0]), "=r"(r[1]), "=r"(r[2]), "=r"(r[3]) : "r"(a));
}
__device__ __forceinline__ void mma16816(float* d, const uint32_t* a, uint32_t b0, uint32_t b1) {
    asm volatile(
        "mma.sync.aligned.m16n8k16.row.col.f32.f16.f16.f32 "
        "{%0,%1,%2,%3}, {%4,%5,%6,%7}, {%8,%9}, {%0,%1,%2,%3};"
        : "+f"(d[0]), "+f"(d[1]), "+f"(d[2]), "+f"(d[3])
        : "r"(a[0]), "r"(a[1]), "r"(a[2]), "r"(a[3]), "r"(b0), "r"(b1));
}

// load 4 contiguous halves -> float4
__device__ __forceinline__ float4 ld4h(const __half* p) {
    uint2 u = *(const uint2*)p;
    __half2 a = *(__half2*)&u.x;
    __half2 b = *(__half2*)&u.y;
    float2 fa = __half22float2(a), fb = __half22float2(b);
    return make_float4(fa.x, fa.y, fb.x, fb.y);
}
__device__ __forceinline__ void st4h(__half* p, float x, float y, float z, float w) {
    uint2 u;
    *(__half2*)&u.x = __floats2half2_rn(x, y);
    *(__half2*)&u.y = __floats2half2_rn(z, w);
    *(uint2*)p = u;
}

// ---------------------------------------------------------------------------
// Pre-pass
// ---------------------------------------------------------------------------
__global__ void __launch_bounds__(256) conv_x_kernel(const float* __restrict__ x,
                                                     __half* __restrict__ xh, long long n4) {
    long long i = ((long long)blockIdx.x * 256 + threadIdx.x);
    if (i >= n4) return;
    float4 v = *(const float4*)(x + i * 4);
    __half2* o = (__half2*)(xh + i * 4);
    o[0] = __floats2half2_rn(v.x, v.y);
    o[1] = __floats2half2_rn(v.z, v.w);
}

__global__ void __launch_bounds__(256) transw_kernel(const float* __restrict__ w,
                                                     __half* __restrict__ wt, int M) {
    int i = blockIdx.x * 256 + threadIdx.x;
    if (i >= 256 * M) return;
    int k = i / M, m = i - k * M;
    wt[i] = __float2half_rn(w[m * 256 + k]);
}

// ---------------------------------------------------------------------------
// fp16 HMMA GEMM: Y[b][m][p] = sum_k Wt[k][m] * X[b][k][p]
// CTA 128m x 128p, K=256, 8 chunks of 32, cp.async double-buffered,
// ldmatrix.x4.trans fragments. MODE 0:+bias 1:plain 2:BN. OUTH: fp16 output.
// ---------------------------------------------------------------------------
template <int MODE, bool OUTH>
__global__ void __launch_bounds__(256, 2) gemm_h_kernel(
    const __half* __restrict__ Wt, const __half* __restrict__ X, void* __restrict__ Yv,
    int Mtot, long long xbs,
    const float* __restrict__ bias,
    const float* __restrict__ bng, const float* __restrict__ bnb,
    const float* __restrict__ bnm, const float* __restrict__ bnv)
{
    __shared__ __align__(16) char smem[2][16384];

    const int tid = threadIdx.x;
    const int warp = tid >> 5;
    const int lane = tid & 31;
    const int wm = warp >> 1;
    const int wp = warp & 1;
    const long long b = blockIdx.z;
    const int mbase = blockIdx.x * 128;
    const int p0 = blockIdx.y * 128;
    const __half* Wg = Wt + mbase;
    const __half* Xg = X + b * xbs + p0;

    const uint32_t sb = smem_u32(smem);

    float acc[2][8][4];
#pragma unroll
    for (int i = 0; i < 2; i++)
#pragma unroll
        for (int j = 0; j < 8; j++)
#pragma unroll
            for (int l = 0; l < 4; l++) acc[i][j][l] = 0.f;

    auto stage = [&](int c) {
        const int k0 = c * 32;
        const uint32_t base = sb + (uint32_t)(c & 1) * 16384;
#pragma unroll
        for (int q = 0; q < 4; q++) {
            int sid = tid + q * 256;
            int tile = sid >> 9, rem = sid & 511;
            int kr = rem >> 4, s = rem & 15;
            uint32_t sa = base + (uint32_t)tile * 8192 + (uint32_t)kr * 256
                        + (uint32_t)((s ^ (kr & 7)) << 4);
            const __half* g = (tile == 0)
                ? Wg + (long long)(k0 + kr) * Mtot + s * 8
                : Xg + (long long)(k0 + kr) * HW_ + s * 8;
            cp16(sa, g);
        }
        CP_COMMIT();
    };

    stage(0);
    stage(1);

#pragma unroll 1
    for (int c = 0; c < 8; c++) {
        if (c < 7) { CP_WAIT(1); } else { CP_WAIT(0); }
        __syncthreads();
        const uint32_t wtile = sb + (uint32_t)(c & 1) * 16384;
        const uint32_t xtile = wtile + 8192;
#pragma unroll
        for (int ks = 0; ks < 2; ks++) {
            const int kb = ks * 16;
            auto faddr = [&](uint32_t tbase, int col0) -> uint32_t {
                int kr = kb + ((lane >> 4) & 1) * 8 + (lane & 7);
                int seg = (col0 >> 3) + ((lane >> 3) & 1);
                return tbase + (uint32_t)kr * 256 + (uint32_t)(((seg ^ (kr & 7)) & 15) << 4);
            };
            uint32_t A[2][4];
            ldsm4t(A[0], faddr(wtile, wm * 32));
            ldsm4t(A[1], faddr(wtile, wm * 32 + 16));
            uint32_t Bf[4][4];
#pragma unroll
            for (int bi = 0; bi < 4; bi++)
                ldsm4t(Bf[bi], faddr(xtile, wp * 64 + bi * 16));
#pragma unroll
            for (int mf = 0; mf < 2; mf++)
#pragma unroll
                for (int nf = 0; nf < 8; nf++)
                    mma16816(acc[mf][nf], A[mf], Bf[nf >> 1][nf & 1], Bf[nf >> 1][(nf & 1) + 2]);
        }
        __syncthreads();
        if (c + 2 < 8) stage(c + 2);
    }

    const int gr = lane >> 2, tg = lane & 3;
    const long long ybase = b * (long long)Mtot * HW_;
    __half* YH = (__half*)Yv;
    float*  YF = (float*)Yv;
#pragma unroll
    for (int mf = 0; mf < 2; mf++) {
        const int m0 = mbase + wm * 32 + mf * 16 + gr;
        float s0 = 0.f, t0 = 0.f, s1 = 0.f, t1 = 0.f;
        if (MODE == 0) {
            t0 = __ldg(bias + m0); t1 = __ldg(bias + m0 + 8);
        } else if (MODE == 2) {
            s0 = __ldg(bng + m0) * rsqrtf(__ldg(bnv + m0) + 1e-5f);
            t0 = __ldg(bnb + m0) - __ldg(bnm + m0) * s0;
            s1 = __ldg(bng + m0 + 8) * rsqrtf(__ldg(bnv + m0 + 8) + 1e-5f);
            t1 = __ldg(bnb + m0 + 8) - __ldg(bnm + m0 + 8) * s1;
        }
#pragma unroll
        for (int nf = 0; nf < 8; nf++) {
            const int p = p0 + wp * 64 + nf * 8 + tg * 2;
            float2 v0 = make_float2(acc[mf][nf][0], acc[mf][nf][1]);
            float2 v1 = make_float2(acc[mf][nf][2], acc[mf][nf][3]);
            if (MODE == 0) {
                v0.x += t0; v0.y += t0; v1.x += t1; v1.y += t1;
            } else if (MODE == 2) {
                v0.x = fmaf(v0.x, s0, t0); v0.y = fmaf(v0.y, s0, t0);
                v1.x = fmaf(v1.x, s1, t1); v1.y = fmaf(v1.y, s1, t1);
            }
            if (OUTH) {
                *(__half2*)(YH + ybase + (long long)m0 * HW_ + p) = __floats2half2_rn(v0.x, v0.y);
                *(__half2*)(YH + ybase + (long long)(m0 + 8) * HW_ + p) = __floats2half2_rn(v1.x, v1.y);
            } else {
                *(float2*)(YF + ybase + (long long)m0 * HW_ + p) = v0;
                *(float2*)(YF + ybase + (long long)(m0 + 8) * HW_ + p) = v1;
            }
        }
    }
}

// ---------------------------------------------------------------------------
// Window attention: qkv fp16 in, attn image fp16 out. fp32 math in smem.
// ---------------------------------------------------------------------------
#define PITCH 260

__global__ void __launch_bounds__(256) attn_kernel(
    const __half* __restrict__ qkv, const float* __restrict__ table,
    __half* __restrict__ attn_out)
{
    __shared__ float buf0[16 * PITCH];
    __shared__ float buf1[16 * PITCH];

    const int b = blockIdx.y;
    const int win = blockIdx.x;
    const int wy = win >> 6, wx = win & 63;
    const int tid = threadIdx.x;
    const int c = tid;
    const long long base = (long long)b * 768 * HW_ + (long long)(wy * 4) * W_ + wx * 4;

#pragma unroll
    for (int r = 0; r < 4; r++) {
        float4 qv = ld4h(qkv + base + (long long)c * HW_ + r * W_);
        float4 kv = ld4h(qkv + base + (long long)(256 + c) * HW_ + r * W_);
        int t0 = r * 4;
        buf0[(t0 + 0) * PITCH + c] = qv.x; buf0[(t0 + 1) * PITCH + c] = qv.y;
        buf0[(t0 + 2) * PITCH + c] = qv.z; buf0[(t0 + 3) * PITCH + c] = qv.w;
        buf1[(t0 + 0) * PITCH + c] = kv.x; buf1[(t0 + 1) * PITCH + c] = kv.y;
        buf1[(t0 + 2) * PITCH + c] = kv.z; buf1[(t0 + 3) * PITCH + c] = kv.w;
    }
    __syncthreads();

    const int h = tid >> 5;
    const int lane = tid & 31;
    const int t = lane & 15;
    const int dh = lane >> 4;
    const float scale = 0.17677669529663687f;

    float4 qr[8];
#pragma unroll
    for (int i = 0; i < 8; i++)
        qr[i] = *(const float4*)(buf0 + t * PITCH + h * DHEAD_ + i * 4);

    float attn[16];
    float mx = -1e30f;
    const int qi = t >> 2, qj = t & 3;
#pragma unroll
    for (int s = 0; s < 16; s++) {
        float dot = 0.f;
#pragma unroll
        for (int i = 0; i < 8; i++) {
            float4 kr = *(const float4*)(buf1 + s * PITCH + h * DHEAD_ + i * 4);
            dot = fmaf(qr[i].x, kr.x, dot); dot = fmaf(qr[i].y, kr.y, dot);
            dot = fmaf(qr[i].z, kr.z, dot); dot = fmaf(qr[i].w, kr.w, dot);
        }
        int ki = s >> 2, kj = s & 3;
        int idx = (qi - ki + 3) * 7 + (qj - kj + 3);
        attn[s] = fmaf(dot, scale, __ldg(table + idx * 8 + h));
        mx = fmaxf(mx, attn[s]);
    }
    float sum = 0.f;
#pragma unroll
    for (int s = 0; s < 16; s++) { attn[s] = __expf(attn[s] - mx); sum += attn[s]; }
    float inv = 1.f / sum;
#pragma unroll
    for (int s = 0; s < 16; s++) attn[s] *= inv;

    __syncthreads();
#pragma unroll
    for (int r = 0; r < 4; r++) {
        float4 vv = ld4h(qkv + base + (long long)(512 + c) * HW_ + r * W_);
        int t0 = r * 4;
        buf0[(t0 + 0) * PITCH + c] = vv.x; buf0[(t0 + 1) * PITCH + c] = vv.y;
        buf0[(t0 + 2) * PITCH + c] = vv.z; buf0[(t0 + 3) * PITCH + c] = vv.w;
    }
    __syncthreads();

    float o[16];
#pragma unroll
    for (int i = 0; i < 16; i++) o[i] = 0.f;
#pragma unroll
    for (int s = 0; s < 16; s++) {
        float a = attn[s];
#pragma unroll
        for (int i = 0; i < 4; i++) {
            float4 vr = *(const float4*)(buf0 + s * PITCH + h * DHEAD_ + dh * 16 + i * 4);
            o[i * 4 + 0] = fmaf(a, vr.x, o[i * 4 + 0]);
            o[i * 4 + 1] = fmaf(a, vr.y, o[i * 4 + 1]);
            o[i * 4 + 2] = fmaf(a, vr.z, o[i * 4 + 2]);
            o[i * 4 + 3] = fmaf(a, vr.w, o[i * 4 + 3]);
        }
    }
#pragma unroll
    for (int i = 0; i < 16; i++)
        buf1[t * PITCH + h * DHEAD_ + dh * 16 + i] = o[i];
    __syncthreads();

    const long long obase = (long long)(b * 256 + c) * HW_ + (long long)(wy * 4) * W_ + wx * 4;
#pragma unroll
    for (int r = 0; r < 4; r++) {
        int t0 = r * 4;
        st4h(attn_out + obase + r * W_,
             buf1[(t0 + 0) * PITCH + c], buf1[(t0 + 1) * PITCH + c],
             buf1[(t0 + 2) * PITCH + c], buf1[(t0 + 3) * PITCH + c]);
    }
}

// ---------------------------------------------------------------------------
// Fused stencil, all-fp16 I/O: pre = (ax+ay)/4 + v + BN(dw3x3(vg))
// ---------------------------------------------------------------------------
__global__ void __launch_bounds__(256) fuse_kernel(
    const __half* __restrict__ attn, const __half* __restrict__ qkv,
    const __half* __restrict__ vg, const float* __restrict__ dw,
    const float* __restrict__ g, const float* __restrict__ bb,
    const float* __restrict__ mm, const float* __restrict__ vv,
    __half* __restrict__ pre)
{
    const int j0 = threadIdx.x << 2;
    const int i  = blockIdx.y * 4 + threadIdx.y;
    const int bc = blockIdx.z;
    const int c = bc & 255;
    const int b = bc >> 8;
    const __half* A  = attn + (long long)bc * HW_;
    const __half* VG = vg + (long long)bc * HW_;
    const __half* V  = qkv + (long long)(b * 768 + 512 + c) * HW_;

    float4 ax = make_float4(0.f, 0.f, 0.f, 0.f);
    float4 rowi = make_float4(0.f, 0.f, 0.f, 0.f);
#pragma unroll
    for (int dr = -1; dr <= 2; dr++) {
        int r = i + dr;
        bool valid = (r >= 0 && r < 257);
        if (r == 256) r = 254;
        if (valid) {
            float4 t = ld4h(A + r * W_ + j0);
            ax.x += t.x; ax.y += t.y; ax.z += t.z; ax.w += t.w;
            if (dr == 0) rowi = t;
        }
    }

    float c7[7];
    c7[0] = (j0 > 0) ? __half2float(A[i * W_ + j0 - 1]) : 0.f;
    c7[1] = rowi.x; c7[2] = rowi.y; c7[3] = rowi.z; c7[4] = rowi.w;
    if (j0 < 252) {
        __half2 rr = *(const __half2*)(A + i * W_ + j0 + 4);
        float2 fr = __half22float2(rr);
        c7[5] = fr.x; c7[6] = fr.y;
    } else {
        c7[5] = rowi.z; c7[6] = 0.f;
    }
    float4 ay;
    ay.x = c7[0] + c7[1] + c7[2] + c7[3];
    ay.y = c7[1] + c7[2] + c7[3] + c7[4];
    ay.z = c7[2] + c7[3] + c7[4] + c7[5];
    ay.w = c7[3] + c7[4] + c7[5] + c7[6];

    float cv[4] = {0.f, 0.f, 0.f, 0.f};
#pragma unroll
    for (int dr = -1; dr <= 1; dr++) {
        int r = i + dr;
        if (r < 0 || r >= H_) continue;
        float w0 = __ldg(dw + c * 9 + (dr + 1) * 3 + 0);
        float w1 = __ldg(dw + c * 9 + (dr + 1) * 3 + 1);
        float w2 = __ldg(dw + c * 9 + (dr + 1) * 3 + 2);
        float cc[6];
        cc[0] = (j0 > 0) ? __half2float(VG[r * W_ + j0 - 1]) : 0.f;
        float4 ctr = ld4h(VG + r * W_ + j0);
        cc[1] = ctr.x; cc[2] = ctr.y; cc[3] = ctr.z; cc[4] = ctr.w;
        cc[5] = (j0 < 252) ? __half2float(VG[r * W_ + j0 + 4]) : 0.f;
#pragma unroll
        for (int l = 0; l < 4; l++)
            cv[l] = fmaf(w0, cc[l], fmaf(w1, cc[l + 1], fmaf(w2, cc[l + 2], cv[l])));
    }

    float4 v4 = ld4h(V + i * W_ + j0);
    float s  = __ldg(g + c) * rsqrtf(__ldg(vv + c) + 1e-5f);
    float tt = __ldg(bb + c) - __ldg(mm + c) * s;

    float rx = (ax.x + ay.x) * 0.25f + v4.x + fmaf(cv[0], s, tt);
    float ry = (ax.y + ay.y) * 0.25f + v4.y + fmaf(cv[1], s, tt);
    float rz = (ax.z + ay.z) * 0.25f + v4.z + fmaf(cv[2], s, tt);
    float rw = (ax.w + ay.w) * 0.25f + v4.w + fmaf(cv[3], s, tt);
    st4h(pre + (long long)bc * HW_ + i * W_ + j0, rx, ry, rz, rw);
}

// ---------------------------------------------------------------------------
extern "C" void kernel_launch(void* const* d_in, const int* in_sizes, int n_in,
                              void* d_out, int out_size)
{
    const float* x        = (const float*)d_in[0];
    const float* qkv_w    = (const float*)d_in[1];
    const float* qkv_b    = (const float*)d_in[2];
    const float* rel_tab  = (const float*)d_in[3];
    const float* gaze_pw  = (const float*)d_in[4];
    const float* gaze_dw  = (const float*)d_in[5];
    const float* gbn_g    = (const float*)d_in[6];
    const float* gbn_b    = (const float*)d_in[7];
    const float* gbn_m    = (const float*)d_in[8];
    const float* gbn_v    = (const float*)d_in[9];
    const float* proj_w   = (const float*)d_in[10];
    const float* pbn_g    = (const float*)d_in[11];
    const float* pbn_b    = (const float*)d_in[12];
    const float* pbn_m    = (const float*)d_in[13];
    const float* pbn_v    = (const float*)d_in[14];
    float* out = (float*)d_out;

    __half *qkvh, *attnh, *vgh, *preh, *xh, *wtq, *wtg, *wtp;
    cudaGetSymbolAddress((void**)&qkvh, d_qkvh_);
    cudaGetSymbolAddress((void**)&attnh, d_attnh_);
    cudaGetSymbolAddress((void**)&vgh, d_vgh_);
    cudaGetSymbolAddress((void**)&preh, d_preh_);
    cudaGetSymbolAddress((void**)&xh, d_xh_);
    cudaGetSymbolAddress((void**)&wtq, d_wtq_);
    cudaGetSymbolAddress((void**)&wtg, d_wtg_);
    cudaGetSymbolAddress((void**)&wtp, d_wtp_);

    // 0) pre-pass
    conv_x_kernel<<<(int)(((long long)B_ * C_ * HW_ / 4 + 255) / 256), 256>>>(
        x, xh, (long long)B_ * C_ * HW_ / 4);
    transw_kernel<<<(256 * 768 + 255) / 256, 256>>>(qkv_w, wtq, 768);
    transw_kernel<<<(256 * 256 + 255) / 256, 256>>>(gaze_pw, wtg, 256);
    transw_kernel<<<(256 * 256 + 255) / 256, 256>>>(proj_w, wtp, 256);

    // 1) qkv(fp16) = qkv_w @ x + b
    gemm_h_kernel<0, true><<<dim3(768 / 128, HW_ / 128, B_), 256>>>(
        wtq, xh, qkvh, 768, (long long)C_ * HW_,
        qkv_b, nullptr, nullptr, nullptr, nullptr);

    // 2) window attention (fp16 I/O, fp32 math)
    attn_kernel<<<dim3(4096, B_), 256>>>(qkvh, rel_tab, attnh);

    // 3) vg(fp16) = gaze_pw @ v   (v = qkv slice [512:768], in place)
    gemm_h_kernel<1, true><<<dim3(256 / 128, HW_ / 128, B_), 256>>>(
        wtg, qkvh + (long long)512 * HW_, vgh, 256, (long long)768 * HW_,
        nullptr, nullptr, nullptr, nullptr, nullptr);

    // 4) pre(fp16) = (ax+ay)/4 + v + BN(dw3x3(vg))
    fuse_kernel<<<dim3(1, H_ / 4, B_ * C_), dim3(64, 4)>>>(
        attnh, qkvh, vgh, gaze_dw, gbn_g, gbn_b, gbn_m, gbn_v, preh);

    // 5) out(fp32) = BN(proj_w @ pre)
    gemm_h_kernel<2, false><<<dim3(256 / 128, HW_ / 128, B_), 256>>>(
        wtp, preh, out, 256, (long long)C_ * HW_,
        nullptr, pbn_g, pbn_b, pbn_m, pbn_v);
}

// round 6
// speedup vs baseline: 3.1629x; 1.0121x over previous
#include <cuda_runtime.h>
#include <cuda_fp16.h>
#include <cstdint>

#define B_   4
#define C_   256
#define H_   256
#define W_   256
#define HW_  65536
#define DHEAD_ 32

// Scratch (device globals; uint4 for 16B alignment)
__device__ uint4 d_qkvh_[(long long)B_ * 768 * HW_ / 8];
__device__ uint4 d_attnh_[(long long)B_ * C_ * HW_ / 8];
__device__ uint4 d_vgh_[(long long)B_ * C_ * HW_ / 8];
__device__ uint4 d_preh_[(long long)B_ * C_ * HW_ / 8];
__device__ uint4 d_xh_[(long long)B_ * C_ * HW_ / 8];
__device__ uint4 d_wtq_[768 * 256 / 8];
__device__ uint4 d_wtg_[256 * 256 / 8];
__device__ uint4 d_wtp_[256 * 256 / 8];

// ---------------------------------------------------------------------------
__device__ __forceinline__ uint32_t smem_u32(const void* p) {
    uint32_t a;
    asm("{ .reg .u64 t; cvta.to.shared.u64 t, %1; cvt.u32.u64 %0, t; }" : "=r"(a) : "l"(p));
    return a;
}
__device__ __forceinline__ void cp16(uint32_t s, const void* g) {
    asm volatile("cp.async.cg.shared.global [%0], [%1], 16;" :: "r"(s), "l"(g));
}
#define CP_COMMIT() asm volatile("cp.async.commit_group;" ::: "memory")
#define CP_WAIT(N)  asm volatile("cp.async.wait_group %0;" :: "n"(N) : "memory")

__device__ __forceinline__ void ldsm4t(uint32_t* r, uint32_t a) {
    asm volatile("ldmatrix.sync.aligned.m8n8.x4.trans.shared.b16 {%0,%1,%2,%3}, [%4];"
                 : "=r"(r[0]), "=r"(r[1]), "=r"(r[2]), "=r"(r[3]) : "r"(a));
}
__device__ __forceinline__ void mma16816(float* d, const uint32_t* a, uint32_t b0, uint32_t b1) {
    asm volatile(
        "mma.sync.aligned.m16n8k16.row.col.f32.f16.f16.f32 "
        "{%0,%1,%2,%3}, {%4,%5,%6,%7}, {%8,%9}, {%0,%1,%2,%3};"
        : "+f"(d[0]), "+f"(d[1]), "+f"(d[2]), "+f"(d[3])
        : "r"(a[0]), "r"(a[1]), "r"(a[2]), "r"(a[3]), "r"(b0), "r"(b1));
}

__device__ __forceinline__ float4 ld4h(const __half* p) {
    uint2 u = *(const uint2*)p;
    __half2 a = *(__half2*)&u.x;
    __half2 b = *(__half2*)&u.y;
    float2 fa = __half22float2(a), fb = __half22float2(b);
    return make_float4(fa.x, fa.y, fb.x, fb.y);
}
__device__ __forceinline__ void st4h(__half* p, float x, float y, float z, float w) {
    uint2 u;
    *(__half2*)&u.x = __floats2half2_rn(x, y);
    *(__half2*)&u.y = __floats2half2_rn(z, w);
    *(uint2*)p = u;
}

// ---------------------------------------------------------------------------
// Pre-pass
// ---------------------------------------------------------------------------
__global__ void __launch_bounds__(256) conv_x_kernel(const float* __restrict__ x,
                                                     __half* __restrict__ xh, long long n4) {
    long long i = ((long long)blockIdx.x * 256 + threadIdx.x);
    if (i >= n4) return;
    float4 v = *(const float4*)(x + i * 4);
    __half2* o = (__half2*)(xh + i * 4);
    o[0] = __floats2half2_rn(v.x, v.y);
    o[1] = __floats2half2_rn(v.z, v.w);
}

__global__ void __launch_bounds__(256) transw_kernel(const float* __restrict__ w,
                                                     __half* __restrict__ wt, int M) {
    int i = blockIdx.x * 256 + threadIdx.x;
    if (i >= 256 * M) return;
    int k = i / M, m = i - k * M;
    wt[i] = __float2half_rn(w[m * 256 + k]);
}

// ---------------------------------------------------------------------------
// fp16 HMMA GEMM, 4-stage cp.async pipeline.
// Y[b][m][p] = sum_k Wt[k][m] * X[b][k][p]; CTA 128m x 128p; K=256 (8 x 32).
// Dynamic smem: 4 stages x (8KB Wtile + 8KB Xtile) = 64KB.
// MODE 0:+bias 1:plain 2:BN.  OUTH: fp16 output.
// ---------------------------------------------------------------------------
template <int MODE, bool OUTH>
__global__ void __launch_bounds__(256, 2) gemm_h_kernel(
    const __half* __restrict__ Wt, const __half* __restrict__ X, void* __restrict__ Yv,
    int Mtot, long long xbs,
    const float* __restrict__ bias,
    const float* __restrict__ bng, const float* __restrict__ bnb,
    const float* __restrict__ bnm, const float* __restrict__ bnv)
{
    extern __shared__ __align__(16) char smem[];

    const int tid = threadIdx.x;
    const int warp = tid >> 5;
    const int lane = tid & 31;
    const int wm = warp >> 1;
    const int wp = warp & 1;
    const long long b = blockIdx.z;
    const int mbase = blockIdx.x * 128;
    const int p0 = blockIdx.y * 128;
    const __half* Wg = Wt + mbase;
    const __half* Xg = X + b * xbs + p0;

    const uint32_t sb = smem_u32(smem);

    float acc[2][8][4];
#pragma unroll
    for (int i = 0; i < 2; i++)
#pragma unroll
        for (int j = 0; j < 8; j++)
#pragma unroll
            for (int l = 0; l < 4; l++) acc[i][j][l] = 0.f;

    auto stage = [&](int c) {
        const int k0 = c * 32;
        const uint32_t base = sb + (uint32_t)(c & 3) * 16384;
#pragma unroll
        for (int q = 0; q < 4; q++) {
            int sid = tid + q * 256;
            int tile = sid >> 9, rem = sid & 511;
            int kr = rem >> 4, s = rem & 15;
            uint32_t sa = base + (uint32_t)tile * 8192 + (uint32_t)kr * 256
                        + (uint32_t)((s ^ (kr & 7)) << 4);
            const __half* g = (tile == 0)
                ? Wg + (long long)(k0 + kr) * Mtot + s * 8
                : Xg + (long long)(k0 + kr) * HW_ + s * 8;
            cp16(sa, g);
        }
        CP_COMMIT();
    };

    stage(0);
    stage(1);
    stage(2);

#pragma unroll 1
    for (int c = 0; c < 8; c++) {
        CP_WAIT(2);
        __syncthreads();
        const uint32_t wtile = sb + (uint32_t)(c & 3) * 16384;
        const uint32_t xtile = wtile + 8192;
#pragma unroll
        for (int ks = 0; ks < 2; ks++) {
            const int kb = ks * 16;
            auto faddr = [&](uint32_t tbase, int col0) -> uint32_t {
                int kr = kb + ((lane >> 4) & 1) * 8 + (lane & 7);
                int seg = (col0 >> 3) + ((lane >> 3) & 1);
                return tbase + (uint32_t)kr * 256 + (uint32_t)(((seg ^ (kr & 7)) & 15) << 4);
            };
            uint32_t A[2][4];
            ldsm4t(A[0], faddr(wtile, wm * 32));
            ldsm4t(A[1], faddr(wtile, wm * 32 + 16));
            uint32_t Bf[4][4];
#pragma unroll
            for (int bi = 0; bi < 4; bi++)
                ldsm4t(Bf[bi], faddr(xtile, wp * 64 + bi * 16));
#pragma unroll
            for (int mf = 0; mf < 2; mf++)
#pragma unroll
                for (int nf = 0; nf < 8; nf++)
                    mma16816(acc[mf][nf], A[mf], Bf[nf >> 1][nf & 1], Bf[nf >> 1][(nf & 1) + 2]);
        }
        if (c + 3 < 8) stage(c + 3);
        else CP_COMMIT();   // empty group keeps wait_group accounting uniform
    }

    const int gr = lane >> 2, tg = lane & 3;
    const long long ybase = b * (long long)Mtot * HW_;
    __half* YH = (__half*)Yv;
    float*  YF = (float*)Yv;
#pragma unroll
    for (int mf = 0; mf < 2; mf++) {
        const int m0 = mbase + wm * 32 + mf * 16 + gr;
        float s0 = 0.f, t0 = 0.f, s1 = 0.f, t1 = 0.f;
        if (MODE == 0) {
            t0 = __ldg(bias + m0); t1 = __ldg(bias + m0 + 8);
        } else if (MODE == 2) {
            s0 = __ldg(bng + m0) * rsqrtf(__ldg(bnv + m0) + 1e-5f);
            t0 = __ldg(bnb + m0) - __ldg(bnm + m0) * s0;
            s1 = __ldg(bng + m0 + 8) * rsqrtf(__ldg(bnv + m0 + 8) + 1e-5f);
            t1 = __ldg(bnb + m0 + 8) - __ldg(bnm + m0 + 8) * s1;
        }
#pragma unroll
        for (int nf = 0; nf < 8; nf++) {
            const int p = p0 + wp * 64 + nf * 8 + tg * 2;
            float2 v0 = make_float2(acc[mf][nf][0], acc[mf][nf][1]);
            float2 v1 = make_float2(acc[mf][nf][2], acc[mf][nf][3]);
            if (MODE == 0) {
                v0.x += t0; v0.y += t0; v1.x += t1; v1.y += t1;
            } else if (MODE == 2) {
                v0.x = fmaf(v0.x, s0, t0); v0.y = fmaf(v0.y, s0, t0);
                v1.x = fmaf(v1.x, s1, t1); v1.y = fmaf(v1.y, s1, t1);
            }
            if (OUTH) {
                *(__half2*)(YH + ybase + (long long)m0 * HW_ + p) = __floats2half2_rn(v0.x, v0.y);
                *(__half2*)(YH + ybase + (long long)(m0 + 8) * HW_ + p) = __floats2half2_rn(v1.x, v1.y);
            } else {
                *(float2*)(YF + ybase + (long long)m0 * HW_ + p) = v0;
                *(float2*)(YF + ybase + (long long)(m0 + 8) * HW_ + p) = v1;
            }
        }
    }
}

// ---------------------------------------------------------------------------
// Window attention: qkv fp16 in, attn image fp16 out. fp32 math in smem.
// ---------------------------------------------------------------------------
#define PITCH 260

__global__ void __launch_bounds__(256) attn_kernel(
    const __half* __restrict__ qkv, const float* __restrict__ table,
    __half* __restrict__ attn_out)
{
    __shared__ float buf0[16 * PITCH];
    __shared__ float buf1[16 * PITCH];

    const int b = blockIdx.y;
    const int win = blockIdx.x;
    const int wy = win >> 6, wx = win & 63;
    const int tid = threadIdx.x;
    const int c = tid;
    const long long base = (long long)b * 768 * HW_ + (long long)(wy * 4) * W_ + wx * 4;

#pragma unroll
    for (int r = 0; r < 4; r++) {
        float4 qv = ld4h(qkv + base + (long long)c * HW_ + r * W_);
        float4 kv = ld4h(qkv + base + (long long)(256 + c) * HW_ + r * W_);
        int t0 = r * 4;
        buf0[(t0 + 0) * PITCH + c] = qv.x; buf0[(t0 + 1) * PITCH + c] = qv.y;
        buf0[(t0 + 2) * PITCH + c] = qv.z; buf0[(t0 + 3) * PITCH + c] = qv.w;
        buf1[(t0 + 0) * PITCH + c] = kv.x; buf1[(t0 + 1) * PITCH + c] = kv.y;
        buf1[(t0 + 2) * PITCH + c] = kv.z; buf1[(t0 + 3) * PITCH + c] = kv.w;
    }
    __syncthreads();

    const int h = tid >> 5;
    const int lane = tid & 31;
    const int t = lane & 15;
    const int dh = lane >> 4;
    const float scale = 0.17677669529663687f;

    float4 qr[8];
#pragma unroll
    for (int i = 0; i < 8; i++)
        qr[i] = *(const float4*)(buf0 + t * PITCH + h * DHEAD_ + i * 4);

    float attn[16];
    float mx = -1e30f;
    const int qi = t >> 2, qj = t & 3;
#pragma unroll
    for (int s = 0; s < 16; s++) {
        float dot = 0.f;
#pragma unroll
        for (int i = 0; i < 8; i++) {
            float4 kr = *(const float4*)(buf1 + s * PITCH + h * DHEAD_ + i * 4);
            dot = fmaf(qr[i].x, kr.x, dot); dot = fmaf(qr[i].y, kr.y, dot);
            dot = fmaf(qr[i].z, kr.z, dot); dot = fmaf(qr[i].w, kr.w, dot);
        }
        int ki = s >> 2, kj = s & 3;
        int idx = (qi - ki + 3) * 7 + (qj - kj + 3);
        attn[s] = fmaf(dot, scale, __ldg(table + idx * 8 + h));
        mx = fmaxf(mx, attn[s]);
    }
    float sum = 0.f;
#pragma unroll
    for (int s = 0; s < 16; s++) { attn[s] = __expf(attn[s] - mx); sum += attn[s]; }
    float inv = 1.f / sum;
#pragma unroll
    for (int s = 0; s < 16; s++) attn[s] *= inv;

    __syncthreads();
#pragma unroll
    for (int r = 0; r < 4; r++) {
        float4 vv = ld4h(qkv + base + (long long)(512 + c) * HW_ + r * W_);
        int t0 = r * 4;
        buf0[(t0 + 0) * PITCH + c] = vv.x; buf0[(t0 + 1) * PITCH + c] = vv.y;
        buf0[(t0 + 2) * PITCH + c] = vv.z; buf0[(t0 + 3) * PITCH + c] = vv.w;
    }
    __syncthreads();

    float o[16];
#pragma unroll
    for (int i = 0; i < 16; i++) o[i] = 0.f;
#pragma unroll
    for (int s = 0; s < 16; s++) {
        float a = attn[s];
#pragma unroll
        for (int i = 0; i < 4; i++) {
            float4 vr = *(const float4*)(buf0 + s * PITCH + h * DHEAD_ + dh * 16 + i * 4);
            o[i * 4 + 0] = fmaf(a, vr.x, o[i * 4 + 0]);
            o[i * 4 + 1] = fmaf(a, vr.y, o[i * 4 + 1]);
            o[i * 4 + 2] = fmaf(a, vr.z, o[i * 4 + 2]);
            o[i * 4 + 3] = fmaf(a, vr.w, o[i * 4 + 3]);
        }
    }
#pragma unroll
    for (int i = 0; i < 16; i++)
        buf1[t * PITCH + h * DHEAD_ + dh * 16 + i] = o[i];
    __syncthreads();

    const long long obase = (long long)(b * 256 + c) * HW_ + (long long)(wy * 4) * W_ + wx * 4;
#pragma unroll
    for (int r = 0; r < 4; r++) {
        int t0 = r * 4;
        st4h(attn_out + obase + r * W_,
             buf1[(t0 + 0) * PITCH + c], buf1[(t0 + 1) * PITCH + c],
             buf1[(t0 + 2) * PITCH + c], buf1[(t0 + 3) * PITCH + c]);
    }
}

// ---------------------------------------------------------------------------
// Fused stencil, all-fp16 I/O: pre = (ax+ay)/4 + v + BN(dw3x3(vg))
// ---------------------------------------------------------------------------
__global__ void __launch_bounds__(256) fuse_kernel(
    const __half* __restrict__ attn, const __half* __restrict__ qkv,
    const __half* __restrict__ vg, const float* __restrict__ dw,
    const float* __restrict__ g, const float* __restrict__ bb,
    const float* __restrict__ mm, const float* __restrict__ vv,
    __half* __restrict__ pre)
{
    const int j0 = threadIdx.x << 2;
    const int i  = blockIdx.y * 4 + threadIdx.y;
    const int bc = blockIdx.z;
    const int c = bc & 255;
    const int b = bc >> 8;
    const __half* A  = attn + (long long)bc * HW_;
    const __half* VG = vg + (long long)bc * HW_;
    const __half* V  = qkv + (long long)(b * 768 + 512 + c) * HW_;

    float4 ax = make_float4(0.f, 0.f, 0.f, 0.f);
    float4 rowi = make_float4(0.f, 0.f, 0.f, 0.f);
#pragma unroll
    for (int dr = -1; dr <= 2; dr++) {
        int r = i + dr;
        bool valid = (r >= 0 && r < 257);
        if (r == 256) r = 254;
        if (valid) {
            float4 t = ld4h(A + r * W_ + j0);
            ax.x += t.x; ax.y += t.y; ax.z += t.z; ax.w += t.w;
            if (dr == 0) rowi = t;
        }
    }

    float c7[7];
    c7[0] = (j0 > 0) ? __half2float(A[i * W_ + j0 - 1]) : 0.f;
    c7[1] = rowi.x; c7[2] = rowi.y; c7[3] = rowi.z; c7[4] = rowi.w;
    if (j0 < 252) {
        __half2 rr = *(const __half2*)(A + i * W_ + j0 + 4);
        float2 fr = __half22float2(rr);
        c7[5] = fr.x; c7[6] = fr.y;
    } else {
        c7[5] = rowi.z; c7[6] = 0.f;
    }
    float4 ay;
    ay.x = c7[0] + c7[1] + c7[2] + c7[3];
    ay.y = c7[1] + c7[2] + c7[3] + c7[4];
    ay.z = c7[2] + c7[3] + c7[4] + c7[5];
    ay.w = c7[3] + c7[4] + c7[5] + c7[6];

    float cv[4] = {0.f, 0.f, 0.f, 0.f};
#pragma unroll
    for (int dr = -1; dr <= 1; dr++) {
        int r = i + dr;
        if (r < 0 || r >= H_) continue;
        float w0 = __ldg(dw + c * 9 + (dr + 1) * 3 + 0);
        float w1 = __ldg(dw + c * 9 + (dr + 1) * 3 + 1);
        float w2 = __ldg(dw + c * 9 + (dr + 1) * 3 + 2);
        float cc[6];
        cc[0] = (j0 > 0) ? __half2float(VG[r * W_ + j0 - 1]) : 0.f;
        float4 ctr = ld4h(VG + r * W_ + j0);
        cc[1] = ctr.x; cc[2] = ctr.y; cc[3] = ctr.z; cc[4] = ctr.w;
        cc[5] = (j0 < 252) ? __half2float(VG[r * W_ + j0 + 4]) : 0.f;
#pragma unroll
        for (int l = 0; l < 4; l++)
            cv[l] = fmaf(w0, cc[l], fmaf(w1, cc[l + 1], fmaf(w2, cc[l + 2], cv[l])));
    }

    float4 v4 = ld4h(V + i * W_ + j0);
    float s  = __ldg(g + c) * rsqrtf(__ldg(vv + c) + 1e-5f);
    float tt = __ldg(bb + c) - __ldg(mm + c) * s;

    float rx = (ax.x + ay.x) * 0.25f + v4.x + fmaf(cv[0], s, tt);
    float ry = (ax.y + ay.y) * 0.25f + v4.y + fmaf(cv[1], s, tt);
    float rz = (ax.z + ay.z) * 0.25f + v4.z + fmaf(cv[2], s, tt);
    float rw = (ax.w + ay.w) * 0.25f + v4.w + fmaf(cv[3], s, tt);
    st4h(pre + (long long)bc * HW_ + i * W_ + j0, rx, ry, rz, rw);
}

// ---------------------------------------------------------------------------
extern "C" void kernel_launch(void* const* d_in, const int* in_sizes, int n_in,
                              void* d_out, int out_size)
{
    const float* x        = (const float*)d_in[0];
    const float* qkv_w    = (const float*)d_in[1];
    const float* qkv_b    = (const float*)d_in[2];
    const float* rel_tab  = (const float*)d_in[3];
    const float* gaze_pw  = (const float*)d_in[4];
    const float* gaze_dw  = (const float*)d_in[5];
    const float* gbn_g    = (const float*)d_in[6];
    const float* gbn_b    = (const float*)d_in[7];
    const float* gbn_m    = (const float*)d_in[8];
    const float* gbn_v    = (const float*)d_in[9];
    const float* proj_w   = (const float*)d_in[10];
    const float* pbn_g    = (const float*)d_in[11];
    const float* pbn_b    = (const float*)d_in[12];
    const float* pbn_m    = (const float*)d_in[13];
    const float* pbn_v    = (const float*)d_in[14];
    float* out = (float*)d_out;

    __half *qkvh, *attnh, *vgh, *preh, *xh, *wtq, *wtg, *wtp;
    cudaGetSymbolAddress((void**)&qkvh, d_qkvh_);
    cudaGetSymbolAddress((void**)&attnh, d_attnh_);
    cudaGetSymbolAddress((void**)&vgh, d_vgh_);
    cudaGetSymbolAddress((void**)&preh, d_preh_);
    cudaGetSymbolAddress((void**)&xh, d_xh_);
    cudaGetSymbolAddress((void**)&wtq, d_wtq_);
    cudaGetSymbolAddress((void**)&wtg, d_wtg_);
    cudaGetSymbolAddress((void**)&wtp, d_wtp_);

    const int SMEM = 65536;
    cudaFuncSetAttribute(gemm_h_kernel<0, true>, cudaFuncAttributeMaxDynamicSharedMemorySize, SMEM);
    cudaFuncSetAttribute(gemm_h_kernel<1, true>, cudaFuncAttributeMaxDynamicSharedMemorySize, SMEM);
    cudaFuncSetAttribute(gemm_h_kernel<2, false>, cudaFuncAttributeMaxDynamicSharedMemorySize, SMEM);

    // 0) pre-pass
    conv_x_kernel<<<(int)(((long long)B_ * C_ * HW_ / 4 + 255) / 256), 256>>>(
        x, xh, (long long)B_ * C_ * HW_ / 4);
    transw_kernel<<<(256 * 768 + 255) / 256, 256>>>(qkv_w, wtq, 768);
    transw_kernel<<<(256 * 256 + 255) / 256, 256>>>(gaze_pw, wtg, 256);
    transw_kernel<<<(256 * 256 + 255) / 256, 256>>>(proj_w, wtp, 256);

    // 1) qkv(fp16) = qkv_w @ x + b
    gemm_h_kernel<0, true><<<dim3(768 / 128, HW_ / 128, B_), 256, SMEM>>>(
        wtq, xh, qkvh, 768, (long long)C_ * HW_,
        qkv_b, nullptr, nullptr, nullptr, nullptr);

    // 2) window attention
    attn_kernel<<<dim3(4096, B_), 256>>>(qkvh, rel_tab, attnh);

    // 3) vg(fp16) = gaze_pw @ v (in-place slice of qkv)
    gemm_h_kernel<1, true><<<dim3(256 / 128, HW_ / 128, B_), 256, SMEM>>>(
        wtg, qkvh + (long long)512 * HW_, vgh, 256, (long long)768 * HW_,
        nullptr, nullptr, nullptr, nullptr, nullptr);

    // 4) pre(fp16) = (ax+ay)/4 + v + BN(dw3x3(vg))
    fuse_kernel<<<dim3(1, H_ / 4, B_ * C_), dim3(64, 4)>>>(
        attnh, qkvh, vgh, gaze_dw, gbn_g, gbn_b, gbn_m, gbn_v, preh);

    // 5) out(fp32) = BN(proj_w @ pre)
    gemm_h_kernel<2, false><<<dim3(256 / 128, HW_ / 128, B_), 256, SMEM>>>(
        wtp, preh, out, 256, (long long)C_ * HW_,
        nullptr, pbn_g, pbn_b, pbn_m, pbn_v);
}

// round 7
// speedup vs baseline: 3.1680x; 1.0016x over previous
#include <cuda_runtime.h>
#include <cuda_fp16.h>
#include <cstdint>

#define B_   4
#define C_   256
#define H_   256
#define W_   256
#define HW_  65536
#define DHEAD_ 32

// Scratch (device globals; uint4 for 16B alignment)
__device__ uint4 d_qkvh_[(long long)B_ * 768 * HW_ / 8];
__device__ uint4 d_attnh_[(long long)B_ * C_ * HW_ / 8];
__device__ uint4 d_vgh_[(long long)B_ * C_ * HW_ / 8];
__device__ uint4 d_preh_[(long long)B_ * C_ * HW_ / 8];
__device__ uint4 d_xh_[(long long)B_ * C_ * HW_ / 8];
__device__ uint4 d_wtq_[768 * 256 / 8];
__device__ uint4 d_wtg_[256 * 256 / 8];
__device__ uint4 d_wtp_[256 * 256 / 8];

// ---------------------------------------------------------------------------
__device__ __forceinline__ uint32_t smem_u32(const void* p) {
    uint32_t a;
    asm("{ .reg .u64 t; cvta.to.shared.u64 t, %1; cvt.u32.u64 %0, t; }" : "=r"(a) : "l"(p));
    return a;
}
__device__ __forceinline__ void cp16(uint32_t s, const void* g) {
    asm volatile("cp.async.cg.shared.global [%0], [%1], 16;" :: "r"(s), "l"(g));
}
#define CP_COMMIT() asm volatile("cp.async.commit_group;" ::: "memory")
#define CP_WAIT(N)  asm volatile("cp.async.wait_group %0;" :: "n"(N) : "memory")

__device__ __forceinline__ void ldsm4t(uint32_t* r, uint32_t a) {
    asm volatile("ldmatrix.sync.aligned.m8n8.x4.trans.shared.b16 {%0,%1,%2,%3}, [%4];"
                 : "=r"(r[0]), "=r"(r[1]), "=r"(r[2]), "=r"(r[3]) : "r"(a));
}
__device__ __forceinline__ void mma16816(float* d, const uint32_t* a, uint32_t b0, uint32_t b1) {
    asm volatile(
        "mma.sync.aligned.m16n8k16.row.col.f32.f16.f16.f32 "
        "{%0,%1,%2,%3}, {%4,%5,%6,%7}, {%8,%9}, {%0,%1,%2,%3};"
        : "+f"(d[0]), "+f"(d[1]), "+f"(d[2]), "+f"(d[3])
        : "r"(a[0]), "r"(a[1]), "r"(a[2]), "r"(a[3]), "r"(b0), "r"(b1));
}

__device__ __forceinline__ float4 ld4h(const __half* p) {
    uint2 u = *(const uint2*)p;
    __half2 a = *(__half2*)&u.x;
    __half2 b = *(__half2*)&u.y;
    float2 fa = __half22float2(a), fb = __half22float2(b);
    return make_float4(fa.x, fa.y, fb.x, fb.y);
}
__device__ __forceinline__ void st4h(__half* p, float x, float y, float z, float w) {
    uint2 u;
    *(__half2*)&u.x = __floats2half2_rn(x, y);
    *(__half2*)&u.y = __floats2half2_rn(z, w);
    *(uint2*)p = u;
}

// ---------------------------------------------------------------------------
// Pre-pass
// ---------------------------------------------------------------------------
__global__ void __launch_bounds__(256) conv_x_kernel(const float* __restrict__ x,
                                                     __half* __restrict__ xh, long long n4) {
    long long i = ((long long)blockIdx.x * 256 + threadIdx.x);
    if (i >= n4) return;
    float4 v = *(const float4*)(x + i * 4);
    __half2* o = (__half2*)(xh + i * 4);
    o[0] = __floats2half2_rn(v.x, v.y);
    o[1] = __floats2half2_rn(v.z, v.w);
}

__global__ void __launch_bounds__(256) transw_kernel(const float* __restrict__ w,
                                                     __half* __restrict__ wt, int M) {
    int i = blockIdx.x * 256 + threadIdx.x;
    if (i >= 256 * M) return;
    int k = i / M, m = i - k * M;
    wt[i] = __float2half_rn(w[m * 256 + k]);
}

// ---------------------------------------------------------------------------
// fp16 HMMA GEMM, 4-stage cp.async pipeline.
// Y[b][m][p] = sum_k Wt[k][m] * X[b][k][p]; CTA 128m x 128p; K=256 (8 x 32).
// Dynamic smem: 4 stages x (8KB Wtile + 8KB Xtile) = 64KB.
// MODE 0:+bias 1:plain 2:BN.  OUTH: fp16 output.
// ---------------------------------------------------------------------------
template <int MODE, bool OUTH>
__global__ void __launch_bounds__(256, 2) gemm_h_kernel(
    const __half* __restrict__ Wt, const __half* __restrict__ X, void* __restrict__ Yv,
    int Mtot, long long xbs,
    const float* __restrict__ bias,
    const float* __restrict__ bng, const float* __restrict__ bnb,
    const float* __restrict__ bnm, const float* __restrict__ bnv)
{
    extern __shared__ __align__(16) char smem[];

    const int tid = threadIdx.x;
    const int warp = tid >> 5;
    const int lane = tid & 31;
    const int wm = warp >> 1;
    const int wp = warp & 1;
    const long long b = blockIdx.z;
    const int mbase = blockIdx.x * 128;
    const int p0 = blockIdx.y * 128;
    const __half* Wg = Wt + mbase;
    const __half* Xg = X + b * xbs + p0;

    const uint32_t sb = smem_u32(smem);

    float acc[2][8][4];
#pragma unroll
    for (int i = 0; i < 2; i++)
#pragma unroll
        for (int j = 0; j < 8; j++)
#pragma unroll
            for (int l = 0; l < 4; l++) acc[i][j][l] = 0.f;

    auto stage = [&](int c) {
        const int k0 = c * 32;
        const uint32_t base = sb + (uint32_t)(c & 3) * 16384;
#pragma unroll
        for (int q = 0; q < 4; q++) {
            int sid = tid + q * 256;
            int tile = sid >> 9, rem = sid & 511;
            int kr = rem >> 4, s = rem & 15;
            uint32_t sa = base + (uint32_t)tile * 8192 + (uint32_t)kr * 256
                        + (uint32_t)((s ^ (kr & 7)) << 4);
            const __half* g = (tile == 0)
                ? Wg + (long long)(k0 + kr) * Mtot + s * 8
                : Xg + (long long)(k0 + kr) * HW_ + s * 8;
            cp16(sa, g);
        }
        CP_COMMIT();
    };

    stage(0);
    stage(1);
    stage(2);

#pragma unroll 1
    for (int c = 0; c < 8; c++) {
        CP_WAIT(2);
        __syncthreads();
        const uint32_t wtile = sb + (uint32_t)(c & 3) * 16384;
        const uint32_t xtile = wtile + 8192;
#pragma unroll
        for (int ks = 0; ks < 2; ks++) {
            const int kb = ks * 16;
            auto faddr = [&](uint32_t tbase, int col0) -> uint32_t {
                int kr = kb + ((lane >> 4) & 1) * 8 + (lane & 7);
                int seg = (col0 >> 3) + ((lane >> 3) & 1);
                return tbase + (uint32_t)kr * 256 + (uint32_t)(((seg ^ (kr & 7)) & 15) << 4);
            };
            uint32_t A[2][4];
            ldsm4t(A[0], faddr(wtile, wm * 32));
            ldsm4t(A[1], faddr(wtile, wm * 32 + 16));
            uint32_t Bf[4][4];
#pragma unroll
            for (int bi = 0; bi < 4; bi++)
                ldsm4t(Bf[bi], faddr(xtile, wp * 64 + bi * 16));
#pragma unroll
            for (int mf = 0; mf < 2; mf++)
#pragma unroll
                for (int nf = 0; nf < 8; nf++)
                    mma16816(acc[mf][nf], A[mf], Bf[nf >> 1][nf & 1], Bf[nf >> 1][(nf & 1) + 2]);
        }
        if (c + 3 < 8) stage(c + 3);
        else CP_COMMIT();   // empty group keeps wait_group accounting uniform
    }

    const int gr = lane >> 2, tg = lane & 3;
    const long long ybase = b * (long long)Mtot * HW_;
    __half* YH = (__half*)Yv;
    float*  YF = (float*)Yv;
#pragma unroll
    for (int mf = 0; mf < 2; mf++) {
        const int m0 = mbase + wm * 32 + mf * 16 + gr;
        float s0 = 0.f, t0 = 0.f, s1 = 0.f, t1 = 0.f;
        if (MODE == 0) {
            t0 = __ldg(bias + m0); t1 = __ldg(bias + m0 + 8);
        } else if (MODE == 2) {
            s0 = __ldg(bng + m0) * rsqrtf(__ldg(bnv + m0) + 1e-5f);
            t0 = __ldg(bnb + m0) - __ldg(bnm + m0) * s0;
            s1 = __ldg(bng + m0 + 8) * rsqrtf(__ldg(bnv + m0 + 8) + 1e-5f);
            t1 = __ldg(bnb + m0 + 8) - __ldg(bnm + m0 + 8) * s1;
        }
#pragma unroll
        for (int nf = 0; nf < 8; nf++) {
            const int p = p0 + wp * 64 + nf * 8 + tg * 2;
            float2 v0 = make_float2(acc[mf][nf][0], acc[mf][nf][1]);
            float2 v1 = make_float2(acc[mf][nf][2], acc[mf][nf][3]);
            if (MODE == 0) {
                v0.x += t0; v0.y += t0; v1.x += t1; v1.y += t1;
            } else if (MODE == 2) {
                v0.x = fmaf(v0.x, s0, t0); v0.y = fmaf(v0.y, s0, t0);
                v1.x = fmaf(v1.x, s1, t1); v1.y = fmaf(v1.y, s1, t1);
            }
            if (OUTH) {
                *(__half2*)(YH + ybase + (long long)m0 * HW_ + p) = __floats2half2_rn(v0.x, v0.y);
                *(__half2*)(YH + ybase + (long long)(m0 + 8) * HW_ + p) = __floats2half2_rn(v1.x, v1.y);
            } else {
                *(float2*)(YF + ybase + (long long)m0 * HW_ + p) = v0;
                *(float2*)(YF + ybase + (long long)(m0 + 8) * HW_ + p) = v1;
            }
        }
    }
}

// ---------------------------------------------------------------------------
// Window attention: qkv fp16 in, attn image fp16 out. fp32 math in smem.
// ---------------------------------------------------------------------------
#define PITCH 260

__global__ void __launch_bounds__(256) attn_kernel(
    const __half* __restrict__ qkv, const float* __restrict__ table,
    __half* __restrict__ attn_out)
{
    __shared__ float buf0[16 * PITCH];
    __shared__ float buf1[16 * PITCH];

    const int b = blockIdx.y;
    const int win = blockIdx.x;
    const int wy = win >> 6, wx = win & 63;
    const int tid = threadIdx.x;
    const int c = tid;
    const long long base = (long long)b * 768 * HW_ + (long long)(wy * 4) * W_ + wx * 4;

#pragma unroll
    for (int r = 0; r < 4; r++) {
        float4 qv = ld4h(qkv + base + (long long)c * HW_ + r * W_);
        float4 kv = ld4h(qkv + base + (long long)(256 + c) * HW_ + r * W_);
        int t0 = r * 4;
        buf0[(t0 + 0) * PITCH + c] = qv.x; buf0[(t0 + 1) * PITCH + c] = qv.y;
        buf0[(t0 + 2) * PITCH + c] = qv.z; buf0[(t0 + 3) * PITCH + c] = qv.w;
        buf1[(t0 + 0) * PITCH + c] = kv.x; buf1[(t0 + 1) * PITCH + c] = kv.y;
        buf1[(t0 + 2) * PITCH + c] = kv.z; buf1[(t0 + 3) * PITCH + c] = kv.w;
    }
    __syncthreads();

    const int h = tid >> 5;
    const int lane = tid & 31;
    const int t = lane & 15;
    const int dh = lane >> 4;
    const float scale = 0.17677669529663687f;

    float4 qr[8];
#pragma unroll
    for (int i = 0; i < 8; i++)
        qr[i] = *(const float4*)(buf0 + t * PITCH + h * DHEAD_ + i * 4);

    float attn[16];
    float mx = -1e30f;
    const int qi = t >> 2, qj = t & 3;
#pragma unroll
    for (int s = 0; s < 16; s++) {
        float dot = 0.f;
#pragma unroll
        for (int i = 0; i < 8; i++) {
            float4 kr = *(const float4*)(buf1 + s * PITCH + h * DHEAD_ + i * 4);
            dot = fmaf(qr[i].x, kr.x, dot); dot = fmaf(qr[i].y, kr.y, dot);
            dot = fmaf(qr[i].z, kr.z, dot); dot = fmaf(qr[i].w, kr.w, dot);
        }
        int ki = s >> 2, kj = s & 3;
        int idx = (qi - ki + 3) * 7 + (qj - kj + 3);
        attn[s] = fmaf(dot, scale, __ldg(table + idx * 8 + h));
        mx = fmaxf(mx, attn[s]);
    }
    float sum = 0.f;
#pragma unroll
    for (int s = 0; s < 16; s++) { attn[s] = __expf(attn[s] - mx); sum += attn[s]; }
    float inv = 1.f / sum;
#pragma unroll
    for (int s = 0; s < 16; s++) attn[s] *= inv;

    __syncthreads();
#pragma unroll
    for (int r = 0; r < 4; r++) {
        float4 vv = ld4h(qkv + base + (long long)(512 + c) * HW_ + r * W_);
        int t0 = r * 4;
        buf0[(t0 + 0) * PITCH + c] = vv.x; buf0[(t0 + 1) * PITCH + c] = vv.y;
        buf0[(t0 + 2) * PITCH + c] = vv.z; buf0[(t0 + 3) * PITCH + c] = vv.w;
    }
    __syncthreads();

    float o[16];
#pragma unroll
    for (int i = 0; i < 16; i++) o[i] = 0.f;
#pragma unroll
    for (int s = 0; s < 16; s++) {
        float a = attn[s];
#pragma unroll
        for (int i = 0; i < 4; i++) {
            float4 vr = *(const float4*)(buf0 + s * PITCH + h * DHEAD_ + dh * 16 + i * 4);
            o[i * 4 + 0] = fmaf(a, vr.x, o[i * 4 + 0]);
            o[i * 4 + 1] = fmaf(a, vr.y, o[i * 4 + 1]);
            o[i * 4 + 2] = fmaf(a, vr.z, o[i * 4 + 2]);
            o[i * 4 + 3] = fmaf(a, vr.w, o[i * 4 + 3]);
        }
    }
#pragma unroll
    for (int i = 0; i < 16; i++)
        buf1[t * PITCH + h * DHEAD_ + dh * 16 + i] = o[i];
    __syncthreads();

    const long long obase = (long long)(b * 256 + c) * HW_ + (long long)(wy * 4) * W_ + wx * 4;
#pragma unroll
    for (int r = 0; r < 4; r++) {
        int t0 = r * 4;
        st4h(attn_out + obase + r * W_,
             buf1[(t0 + 0) * PITCH + c], buf1[(t0 + 1) * PITCH + c],
             buf1[(t0 + 2) * PITCH + c], buf1[(t0 + 3) * PITCH + c]);
    }
}

// ---------------------------------------------------------------------------
// Fused stencil, all-fp16 I/O: pre = (ax+ay)/4 + v + BN(dw3x3(vg))
// ---------------------------------------------------------------------------
__global__ void __launch_bounds__(256) fuse_kernel(
    const __half* __restrict__ attn, const __half* __restrict__ qkv,
    const __half* __restrict__ vg, const float* __restrict__ dw,
    const float* __restrict__ g, const float* __restrict__ bb,
    const float* __restrict__ mm, const float* __restrict__ vv,
    __half* __restrict__ pre)
{
    const int j0 = threadIdx.x << 2;
    const int i  = blockIdx.y * 4 + threadIdx.y;
    const int bc = blockIdx.z;
    const int c = bc & 255;
    const int b = bc >> 8;
    const __half* A  = attn + (long long)bc * HW_;
    const __half* VG = vg + (long long)bc * HW_;
    const __half* V  = qkv + (long long)(b * 768 + 512 + c) * HW_;

    float4 ax = make_float4(0.f, 0.f, 0.f, 0.f);
    float4 rowi = make_float4(0.f, 0.f, 0.f, 0.f);
#pragma unroll
    for (int dr = -1; dr <= 2; dr++) {
        int r = i + dr;
        bool valid = (r >= 0 && r < 257);
        if (r == 256) r = 254;
        if (valid) {
            float4 t = ld4h(A + r * W_ + j0);
            ax.x += t.x; ax.y += t.y; ax.z += t.z; ax.w += t.w;
            if (dr == 0) rowi = t;
        }
    }

    float c7[7];
    c7[0] = (j0 > 0) ? __half2float(A[i * W_ + j0 - 1]) : 0.f;
    c7[1] = rowi.x; c7[2] = rowi.y; c7[3] = rowi.z; c7[4] = rowi.w;
    if (j0 < 252) {
        __half2 rr = *(const __half2*)(A + i * W_ + j0 + 4);
        float2 fr = __half22float2(rr);
        c7[5] = fr.x; c7[6] = fr.y;
    } else {
        c7[5] = rowi.z; c7[6] = 0.f;
    }
    float4 ay;
    ay.x = c7[0] + c7[1] + c7[2] + c7[3];
    ay.y = c7[1] + c7[2] + c7[3] + c7[4];
    ay.z = c7[2] + c7[3] + c7[4] + c7[5];
    ay.w = c7[3] + c7[4] + c7[5] + c7[6];

    float cv[4] = {0.f, 0.f, 0.f, 0.f};
#pragma unroll
    for (int dr = -1; dr <= 1; dr++) {
        int r = i + dr;
        if (r < 0 || r >= H_) continue;
        float w0 = __ldg(dw + c * 9 + (dr + 1) * 3 + 0);
        float w1 = __ldg(dw + c * 9 + (dr + 1) * 3 + 1);
        float w2 = __ldg(dw + c * 9 + (dr + 1) * 3 + 2);
        float cc[6];
        cc[0] = (j0 > 0) ? __half2float(VG[r * W_ + j0 - 1]) : 0.f;
        float4 ctr = ld4h(VG + r * W_ + j0);
        cc[1] = ctr.x; cc[2] = ctr.y; cc[3] = ctr.z; cc[4] = ctr.w;
        cc[5] = (j0 < 252) ? __half2float(VG[r * W_ + j0 + 4]) : 0.f;
#pragma unroll
        for (int l = 0; l < 4; l++)
            cv[l] = fmaf(w0, cc[l], fmaf(w1, cc[l + 1], fmaf(w2, cc[l + 2], cv[l])));
    }

    float4 v4 = ld4h(V + i * W_ + j0);
    float s  = __ldg(g + c) * rsqrtf(__ldg(vv + c) + 1e-5f);
    float tt = __ldg(bb + c) - __ldg(mm + c) * s;

    float rx = (ax.x + ay.x) * 0.25f + v4.x + fmaf(cv[0], s, tt);
    float ry = (ax.y + ay.y) * 0.25f + v4.y + fmaf(cv[1], s, tt);
    float rz = (ax.z + ay.z) * 0.25f + v4.z + fmaf(cv[2], s, tt);
    float rw = (ax.w + ay.w) * 0.25f + v4.w + fmaf(cv[3], s, tt);
    st4h(pre + (long long)bc * HW_ + i * W_ + j0, rx, ry, rz, rw);
}

// ---------------------------------------------------------------------------
extern "C" void kernel_launch(void* const* d_in, const int* in_sizes, int n_in,
                              void* d_out, int out_size)
{
    const float* x        = (const float*)d_in[0];
    const float* qkv_w    = (const float*)d_in[1];
    const float* qkv_b    = (const float*)d_in[2];
    const float* rel_tab  = (const float*)d_in[3];
    const float* gaze_pw  = (const float*)d_in[4];
    const float* gaze_dw  = (const float*)d_in[5];
    const float* gbn_g    = (const float*)d_in[6];
    const float* gbn_b    = (const float*)d_in[7];
    const float* gbn_m    = (const float*)d_in[8];
    const float* gbn_v    = (const float*)d_in[9];
    const float* proj_w   = (const float*)d_in[10];
    const float* pbn_g    = (const float*)d_in[11];
    const float* pbn_b    = (const float*)d_in[12];
    const float* pbn_m    = (const float*)d_in[13];
    const float* pbn_v    = (const float*)d_in[14];
    float* out = (float*)d_out;

    __half *qkvh, *attnh, *vgh, *preh, *xh, *wtq, *wtg, *wtp;
    cudaGetSymbolAddress((void**)&qkvh, d_qkvh_);
    cudaGetSymbolAddress((void**)&attnh, d_attnh_);
    cudaGetSymbolAddress((void**)&vgh, d_vgh_);
    cudaGetSymbolAddress((void**)&preh, d_preh_);
    cudaGetSymbolAddress((void**)&xh, d_xh_);
    cudaGetSymbolAddress((void**)&wtq, d_wtq_);
    cudaGetSymbolAddress((void**)&wtg, d_wtg_);
    cudaGetSymbolAddress((void**)&wtp, d_wtp_);

    const int SMEM = 65536;
    cudaFuncSetAttribute(gemm_h_kernel<0, true>, cudaFuncAttributeMaxDynamicSharedMemorySize, SMEM);
    cudaFuncSetAttribute(gemm_h_kernel<1, true>, cudaFuncAttributeMaxDynamicSharedMemorySize, SMEM);
    cudaFuncSetAttribute(gemm_h_kernel<2, false>, cudaFuncAttributeMaxDynamicSharedMemorySize, SMEM);

    // 0) pre-pass
    conv_x_kernel<<<(int)(((long long)B_ * C_ * HW_ / 4 + 255) / 256), 256>>>(
        x, xh, (long long)B_ * C_ * HW_ / 4);
    transw_kernel<<<(256 * 768 + 255) / 256, 256>>>(qkv_w, wtq, 768);
    transw_kernel<<<(256 * 256 + 255) / 256, 256>>>(gaze_pw, wtg, 256);
    transw_kernel<<<(256 * 256 + 255) / 256, 256>>>(proj_w, wtp, 256);

    // 1) qkv(fp16) = qkv_w @ x + b
    gemm_h_kernel<0, true><<<dim3(768 / 128, HW_ / 128, B_), 256, SMEM>>>(
        wtq, xh, qkvh, 768, (long long)C_ * HW_,
        qkv_b, nullptr, nullptr, nullptr, nullptr);

    // 2) window attention
    attn_kernel<<<dim3(4096, B_), 256>>>(qkvh, rel_tab, attnh);

    // 3) vg(fp16) = gaze_pw @ v (in-place slice of qkv)
    gemm_h_kernel<1, true><<<dim3(256 / 128, HW_ / 128, B_), 256, SMEM>>>(
        wtg, qkvh + (long long)512 * HW_, vgh, 256, (long long)768 * HW_,
        nullptr, nullptr, nullptr, nullptr, nullptr);

    // 4) pre(fp16) = (ax+ay)/4 + v + BN(dw3x3(vg))
    fuse_kernel<<<dim3(1, H_ / 4, B_ * C_), dim3(64, 4)>>>(
        attnh, qkvh, vgh, gaze_dw, gbn_g, gbn_b, gbn_m, gbn_v, preh);

    // 5) out(fp32) = BN(proj_w @ pre)
    gemm_h_kernel<2, false><<<dim3(256 / 128, HW_ / 128, B_), 256, SMEM>>>(
        wtp, preh, out, 256, (long long)C_ * HW_,
        nullptr, pbn_g, pbn_b, pbn_m, pbn_v);
}

// round 8
// speedup vs baseline: 4.0478x; 1.2777x over previous
#include <cuda_runtime.h>
#include <cuda_fp16.h>
#include <cstdint>

#define B_   4
#define C_   256
#define H_   256
#define W_   256
#define HW_  65536

// Scratch (device globals; uint4 for 16B alignment)
__device__ uint4 d_qkvh_[(long long)B_ * 768 * HW_ / 8];
__device__ uint4 d_attnh_[(long long)B_ * C_ * HW_ / 8];
__device__ uint4 d_vgh_[(long long)B_ * C_ * HW_ / 8];
__device__ uint4 d_preh_[(long long)B_ * C_ * HW_ / 8];
__device__ uint4 d_xh_[(long long)B_ * C_ * HW_ / 8];
__device__ uint4 d_wtq_[768 * 256 / 8];
__device__ uint4 d_wtg_[256 * 256 / 8];
__device__ uint4 d_wtp_[256 * 256 / 8];

// ---------------------------------------------------------------------------
__device__ __forceinline__ uint32_t smem_u32(const void* p) {
    uint32_t a;
    asm("{ .reg .u64 t; cvta.to.shared.u64 t, %1; cvt.u32.u64 %0, t; }" : "=r"(a) : "l"(p));
    return a;
}
__device__ __forceinline__ void cp16(uint32_t s, const void* g) {
    asm volatile("cp.async.cg.shared.global [%0], [%1], 16;" :: "r"(s), "l"(g));
}
#define CP_COMMIT() asm volatile("cp.async.commit_group;" ::: "memory")
#define CP_WAIT(N)  asm volatile("cp.async.wait_group %0;" :: "n"(N) : "memory")

__device__ __forceinline__ void ldsm4t(uint32_t* r, uint32_t a) {
    asm volatile("ldmatrix.sync.aligned.m8n8.x4.trans.shared.b16 {%0,%1,%2,%3}, [%4];"
                 : "=r"(r[0]), "=r"(r[1]), "=r"(r[2]), "=r"(r[3]) : "r"(a));
}
__device__ __forceinline__ void mma16816(float* d, const uint32_t* a, uint32_t b0, uint32_t b1) {
    asm volatile(
        "mma.sync.aligned.m16n8k16.row.col.f32.f16.f16.f32 "
        "{%0,%1,%2,%3}, {%4,%5,%6,%7}, {%8,%9}, {%0,%1,%2,%3};"
        : "+f"(d[0]), "+f"(d[1]), "+f"(d[2]), "+f"(d[3])
        : "r"(a[0]), "r"(a[1]), "r"(a[2]), "r"(a[3]), "r"(b0), "r"(b1));
}
__device__ __forceinline__ float4 ld4h(const __half* p) {
    uint2 u = *(const uint2*)p;
    __half2 a = *(__half2*)&u.x;
    __half2 b = *(__half2*)&u.y;
    float2 fa = __half22float2(a), fb = __half22float2(b);
    return make_float4(fa.x, fa.y, fb.x, fb.y);
}
__device__ __forceinline__ void st4h(__half* p, float x, float y, float z, float w) {
    uint2 u;
    *(__half2*)&u.x = __floats2half2_rn(x, y);
    *(__half2*)&u.y = __floats2half2_rn(z, w);
    *(uint2*)p = u;
}
__device__ __forceinline__ uint32_t packh2(float a, float b) {
    __half2 h = __floats2half2_rn(a, b);
    return *(uint32_t*)&h;
}

// ---------------------------------------------------------------------------
// Pre-pass
// ---------------------------------------------------------------------------
__global__ void __launch_bounds__(256) conv_x_kernel(const float* __restrict__ x,
                                                     __half* __restrict__ xh, long long n4) {
    long long i = ((long long)blockIdx.x * 256 + threadIdx.x);
    if (i >= n4) return;
    float4 v = *(const float4*)(x + i * 4);
    __half2* o = (__half2*)(xh + i * 4);
    o[0] = __floats2half2_rn(v.x, v.y);
    o[1] = __floats2half2_rn(v.z, v.w);
}

__global__ void __launch_bounds__(256) transw_kernel(const float* __restrict__ w,
                                                     __half* __restrict__ wt, int M) {
    int i = blockIdx.x * 256 + threadIdx.x;
    if (i >= 256 * M) return;
    int k = i / M, m = i - k * M;
    wt[i] = __float2half_rn(w[m * 256 + k]);
}

// ---------------------------------------------------------------------------
// fp16 HMMA GEMM (unchanged from best R5): 4-stage cp.async pipeline.
// ---------------------------------------------------------------------------
template <int MODE, bool OUTH>
__global__ void __launch_bounds__(256, 2) gemm_h_kernel(
    const __half* __restrict__ Wt, const __half* __restrict__ X, void* __restrict__ Yv,
    int Mtot, long long xbs,
    const float* __restrict__ bias,
    const float* __restrict__ bng, const float* __restrict__ bnb,
    const float* __restrict__ bnm, const float* __restrict__ bnv)
{
    extern __shared__ __align__(16) char smem[];

    const int tid = threadIdx.x;
    const int warp = tid >> 5;
    const int lane = tid & 31;
    const int wm = warp >> 1;
    const int wp = warp & 1;
    const long long b = blockIdx.z;
    const int mbase = blockIdx.x * 128;
    const int p0 = blockIdx.y * 128;
    const __half* Wg = Wt + mbase;
    const __half* Xg = X + b * xbs + p0;

    const uint32_t sb = smem_u32(smem);

    float acc[2][8][4];
#pragma unroll
    for (int i = 0; i < 2; i++)
#pragma unroll
        for (int j = 0; j < 8; j++)
#pragma unroll
            for (int l = 0; l < 4; l++) acc[i][j][l] = 0.f;

    auto stage = [&](int c) {
        const int k0 = c * 32;
        const uint32_t base = sb + (uint32_t)(c & 3) * 16384;
#pragma unroll
        for (int q = 0; q < 4; q++) {
            int sid = tid + q * 256;
            int tile = sid >> 9, rem = sid & 511;
            int kr = rem >> 4, s = rem & 15;
            uint32_t sa = base + (uint32_t)tile * 8192 + (uint32_t)kr * 256
                        + (uint32_t)((s ^ (kr & 7)) << 4);
            const __half* g = (tile == 0)
                ? Wg + (long long)(k0 + kr) * Mtot + s * 8
                : Xg + (long long)(k0 + kr) * HW_ + s * 8;
            cp16(sa, g);
        }
        CP_COMMIT();
    };

    stage(0);
    stage(1);
    stage(2);

#pragma unroll 1
    for (int c = 0; c < 8; c++) {
        CP_WAIT(2);
        __syncthreads();
        const uint32_t wtile = sb + (uint32_t)(c & 3) * 16384;
        const uint32_t xtile = wtile + 8192;
#pragma unroll
        for (int ks = 0; ks < 2; ks++) {
            const int kb = ks * 16;
            auto faddr = [&](uint32_t tbase, int col0) -> uint32_t {
                int kr = kb + ((lane >> 4) & 1) * 8 + (lane & 7);
                int seg = (col0 >> 3) + ((lane >> 3) & 1);
                return tbase + (uint32_t)kr * 256 + (uint32_t)(((seg ^ (kr & 7)) & 15) << 4);
            };
            uint32_t A[2][4];
            ldsm4t(A[0], faddr(wtile, wm * 32));
            ldsm4t(A[1], faddr(wtile, wm * 32 + 16));
            uint32_t Bf[4][4];
#pragma unroll
            for (int bi = 0; bi < 4; bi++)
                ldsm4t(Bf[bi], faddr(xtile, wp * 64 + bi * 16));
#pragma unroll
            for (int mf = 0; mf < 2; mf++)
#pragma unroll
                for (int nf = 0; nf < 8; nf++)
                    mma16816(acc[mf][nf], A[mf], Bf[nf >> 1][nf & 1], Bf[nf >> 1][(nf & 1) + 2]);
        }
        if (c + 3 < 8) stage(c + 3);
        else CP_COMMIT();
    }

    const int gr = lane >> 2, tg = lane & 3;
    const long long ybase = b * (long long)Mtot * HW_;
    __half* YH = (__half*)Yv;
    float*  YF = (float*)Yv;
#pragma unroll
    for (int mf = 0; mf < 2; mf++) {
        const int m0 = mbase + wm * 32 + mf * 16 + gr;
        float s0 = 0.f, t0 = 0.f, s1 = 0.f, t1 = 0.f;
        if (MODE == 0) {
            t0 = __ldg(bias + m0); t1 = __ldg(bias + m0 + 8);
        } else if (MODE == 2) {
            s0 = __ldg(bng + m0) * rsqrtf(__ldg(bnv + m0) + 1e-5f);
            t0 = __ldg(bnb + m0) - __ldg(bnm + m0) * s0;
            s1 = __ldg(bng + m0 + 8) * rsqrtf(__ldg(bnv + m0 + 8) + 1e-5f);
            t1 = __ldg(bnb + m0 + 8) - __ldg(bnm + m0 + 8) * s1;
        }
#pragma unroll
        for (int nf = 0; nf < 8; nf++) {
            const int p = p0 + wp * 64 + nf * 8 + tg * 2;
            float2 v0 = make_float2(acc[mf][nf][0], acc[mf][nf][1]);
            float2 v1 = make_float2(acc[mf][nf][2], acc[mf][nf][3]);
            if (MODE == 0) {
                v0.x += t0; v0.y += t0; v1.x += t1; v1.y += t1;
            } else if (MODE == 2) {
                v0.x = fmaf(v0.x, s0, t0); v0.y = fmaf(v0.y, s0, t0);
                v1.x = fmaf(v1.x, s1, t1); v1.y = fmaf(v1.y, s1, t1);
            }
            if (OUTH) {
                *(__half2*)(YH + ybase + (long long)m0 * HW_ + p) = __floats2half2_rn(v0.x, v0.y);
                *(__half2*)(YH + ybase + (long long)(m0 + 8) * HW_ + p) = __floats2half2_rn(v1.x, v1.y);
            } else {
                *(float2*)(YF + ybase + (long long)m0 * HW_ + p) = v0;
                *(float2*)(YF + ybase + (long long)(m0 + 8) * HW_ + p) = v1;
            }
        }
    }
}

// ---------------------------------------------------------------------------
// Window attention via HMMA. Block = 4 adjacent windows (4 rows x 16 px),
// 512 threads (16 warps; warp handles 2 (win,head) tasks).
// smem: qb,kb fp16 [256 ch][72 wtok]; vb fp16 [64 wtok][264 ch]; bias f32 [8][16][16]
// wtok(x,r) = (x>>2)*16 + r*4 + (x&3). o overwrites each task's own K region.
// ---------------------------------------------------------------------------
#define QK_P  72
#define V_P   264
#define SM_QB 0
#define SM_KB 36864
#define SM_VB 73728
#define SM_BS 107520
#define SM_ATTN_TOTAL 115712

__global__ void __launch_bounds__(512, 1) attn_kernel(
    const __half* __restrict__ qkv, const float* __restrict__ table,
    __half* __restrict__ attn_out)
{
    extern __shared__ __align__(16) char sm[];
    __half* qb = (__half*)(sm + SM_QB);
    __half* kb = (__half*)(sm + SM_KB);
    __half* vb = (__half*)(sm + SM_VB);
    float*  bs = (float*)(sm + SM_BS);

    const int tid = threadIdx.x;
    const int b = blockIdx.y;
    const int strip = blockIdx.x;
    const int wy = strip >> 4, wsx = strip & 15;
    const int c = tid & 255;
    const int hlf = tid >> 8;
    const long long gbase = (long long)b * 768 * HW_ + (long long)(wy * 4) * W_ + wsx * 16;

    // stage rel-bias: [head][qt][st]
#pragma unroll
    for (int it = 0; it < 4; it++) {
        int id = tid + it * 512;
        int h = id >> 8, t = (id >> 4) & 15, s = id & 15;
        int idx = ((t >> 2) - (s >> 2) + 3) * 7 + ((t & 3) - (s & 3) + 3);
        bs[id] = __ldg(table + idx * 8 + h);
    }

    // load q,k,v (coalesced: each thread consumes full 32B sectors)
#pragma unroll
    for (int rr = 0; rr < 2; rr++) {
        int r = hlf * 2 + rr;
        const __half* gq = qkv + gbase + (long long)c * HW_ + r * W_;
#pragma unroll
        for (int seg = 0; seg < 2; seg++) {
            uint4 uq = *(const uint4*)(gq + seg * 8);
            uint4 uk = *(const uint4*)(gq + (long long)256 * HW_ + seg * 8);
            uint4 uv = *(const uint4*)(gq + (long long)512 * HW_ + seg * 8);
            int w0 = seg * 2;
            *(uint2*)(qb + c * QK_P + (w0    ) * 16 + r * 4) = make_uint2(uq.x, uq.y);
            *(uint2*)(qb + c * QK_P + (w0 + 1) * 16 + r * 4) = make_uint2(uq.z, uq.w);
            *(uint2*)(kb + c * QK_P + (w0    ) * 16 + r * 4) = make_uint2(uk.x, uk.y);
            *(uint2*)(kb + c * QK_P + (w0 + 1) * 16 + r * 4) = make_uint2(uk.z, uk.w);
            __half* vh8 = (__half*)&uv;
#pragma unroll
            for (int j = 0; j < 8; j++) {
                int x = seg * 8 + j;
                int wt = (x >> 2) * 16 + r * 4 + (x & 3);
                vb[wt * V_P + c] = vh8[j];
            }
        }
    }
    __syncthreads();

    const int warp = tid >> 5;
    const int lane = tid & 31;
    const int krow_off = ((lane >> 4) & 1) * 8 + (lane & 7);
    const int colsel = (lane >> 3) & 1;
    const int t0 = lane >> 2, t1 = t0 + 8;
    const int sbase = (lane & 3) * 2;
    const float scale = 0.17677669529663687f;
    const uint32_t qbu = smem_u32(qb), kbu = smem_u32(kb), vbu = smem_u32(vb);

#pragma unroll
    for (int ti = 0; ti < 2; ti++) {
        const int task = warp * 2 + ti;
        const int win = task >> 3, head = task & 7;
        const int tb = win * 16;
        const int hb = head * 32;

        uint32_t Aq[2][4], Bk[2][4];
#pragma unroll
        for (int kc = 0; kc < 2; kc++) {
            uint32_t off = (uint32_t)(hb + kc * 16 + krow_off) * (QK_P * 2)
                         + (uint32_t)(tb * 2 + colsel * 16);
            ldsm4t(Aq[kc], qbu + off);
            ldsm4t(Bk[kc], kbu + off);
        }
        float sc0[4] = {0.f, 0.f, 0.f, 0.f}, sc1[4] = {0.f, 0.f, 0.f, 0.f};
#pragma unroll
        for (int kc = 0; kc < 2; kc++) {
            mma16816(sc0, Aq[kc], Bk[kc][0], Bk[kc][2]);
            mma16816(sc1, Aq[kc], Bk[kc][1], Bk[kc][3]);
        }
        const float* bh = bs + head * 256;
        sc0[0] = fmaf(sc0[0], scale, bh[t0 * 16 + sbase]);
        sc0[1] = fmaf(sc0[1], scale, bh[t0 * 16 + sbase + 1]);
        sc0[2] = fmaf(sc0[2], scale, bh[t1 * 16 + sbase]);
        sc0[3] = fmaf(sc0[3], scale, bh[t1 * 16 + sbase + 1]);
        sc1[0] = fmaf(sc1[0], scale, bh[t0 * 16 + 8 + sbase]);
        sc1[1] = fmaf(sc1[1], scale, bh[t0 * 16 + 8 + sbase + 1]);
        sc1[2] = fmaf(sc1[2], scale, bh[t1 * 16 + 8 + sbase]);
        sc1[3] = fmaf(sc1[3], scale, bh[t1 * 16 + 8 + sbase + 1]);

        // softmax over rows t0 / t1 (16 s-values spread over quad lanes)
        float m0 = fmaxf(fmaxf(sc0[0], sc0[1]), fmaxf(sc1[0], sc1[1]));
        float m1 = fmaxf(fmaxf(sc0[2], sc0[3]), fmaxf(sc1[2], sc1[3]));
        m0 = fmaxf(m0, __shfl_xor_sync(0xffffffffu, m0, 1));
        m0 = fmaxf(m0, __shfl_xor_sync(0xffffffffu, m0, 2));
        m1 = fmaxf(m1, __shfl_xor_sync(0xffffffffu, m1, 1));
        m1 = fmaxf(m1, __shfl_xor_sync(0xffffffffu, m1, 2));
        sc0[0] = __expf(sc0[0] - m0); sc0[1] = __expf(sc0[1] - m0);
        sc0[2] = __expf(sc0[2] - m1); sc0[3] = __expf(sc0[3] - m1);
        sc1[0] = __expf(sc1[0] - m0); sc1[1] = __expf(sc1[1] - m0);
        sc1[2] = __expf(sc1[2] - m1); sc1[3] = __expf(sc1[3] - m1);
        float u0 = sc0[0] + sc0[1] + sc1[0] + sc1[1];
        float u1 = sc0[2] + sc0[3] + sc1[2] + sc1[3];
        u0 += __shfl_xor_sync(0xffffffffu, u0, 1);
        u0 += __shfl_xor_sync(0xffffffffu, u0, 2);
        u1 += __shfl_xor_sync(0xffffffffu, u1, 1);
        u1 += __shfl_xor_sync(0xffffffffu, u1, 2);
        float inv0 = 1.f / u0, inv1 = 1.f / u1;

        // pack attn weights into A fragment (m=q tokens, k=s tokens)
        uint32_t Ap[4];
        Ap[0] = packh2(sc0[0] * inv0, sc0[1] * inv0);
        Ap[1] = packh2(sc0[2] * inv1, sc0[3] * inv1);
        Ap[2] = packh2(sc1[0] * inv0, sc1[1] * inv0);
        Ap[3] = packh2(sc1[2] * inv1, sc1[3] * inv1);

        // o = attn @ V ; write o into this task's own K region (done with it)
#pragma unroll
        for (int nc = 0; nc < 2; nc++) {
            uint32_t Bv[4];
            uint32_t va = vbu + (uint32_t)(tb + krow_off) * (V_P * 2)
                        + (uint32_t)((hb + nc * 16) * 2 + colsel * 16);
            ldsm4t(Bv, va);
            float oc0[4] = {0.f, 0.f, 0.f, 0.f}, oc1[4] = {0.f, 0.f, 0.f, 0.f};
            mma16816(oc0, Ap, Bv[0], Bv[2]);
            mma16816(oc1, Ap, Bv[1], Bv[3]);
            int ch0 = hb + nc * 16 + sbase;
            kb[(ch0    ) * QK_P + tb + t0] = __float2half_rn(oc0[0]);
            kb[(ch0 + 1) * QK_P + tb + t0] = __float2half_rn(oc0[1]);
            kb[(ch0    ) * QK_P + tb + t1] = __float2half_rn(oc0[2]);
            kb[(ch0 + 1) * QK_P + tb + t1] = __float2half_rn(oc0[3]);
            kb[(ch0 + 8) * QK_P + tb + t0] = __float2half_rn(oc1[0]);
            kb[(ch0 + 9) * QK_P + tb + t0] = __float2half_rn(oc1[1]);
            kb[(ch0 + 8) * QK_P + tb + t1] = __float2half_rn(oc1[2]);
            kb[(ch0 + 9) * QK_P + tb + t1] = __float2half_rn(oc1[3]);
        }
    }
    __syncthreads();

    // coalesced writeout from kb (o lives there now)
#pragma unroll
    for (int rr = 0; rr < 2; rr++) {
        int r = hlf * 2 + rr;
        __half tmp[16];
#pragma unroll
        for (int w = 0; w < 4; w++)
            *(uint2*)(tmp + w * 4) = *(uint2*)(kb + c * QK_P + w * 16 + r * 4);
        __half* dst = attn_out + ((long long)(b * 256 + c)) * HW_
                    + (long long)(wy * 4 + r) * W_ + wsx * 16;
        *(uint4*)(dst)     = *(uint4*)(tmp);
        *(uint4*)(dst + 8) = *(uint4*)(tmp + 8);
    }
}

// ---------------------------------------------------------------------------
// Fused stencil, all-fp16 I/O: pre = (ax+ay)/4 + v + BN(dw3x3(vg))
// ---------------------------------------------------------------------------
__global__ void __launch_bounds__(256) fuse_kernel(
    const __half* __restrict__ attn, const __half* __restrict__ qkv,
    const __half* __restrict__ vg, const float* __restrict__ dw,
    const float* __restrict__ g, const float* __restrict__ bb,
    const float* __restrict__ mm, const float* __restrict__ vv,
    __half* __restrict__ pre)
{
    const int j0 = threadIdx.x << 2;
    const int i  = blockIdx.y * 4 + threadIdx.y;
    const int bc = blockIdx.z;
    const int c = bc & 255;
    const int b = bc >> 8;
    const __half* A  = attn + (long long)bc * HW_;
    const __half* VG = vg + (long long)bc * HW_;
    const __half* V  = qkv + (long long)(b * 768 + 512 + c) * HW_;

    float4 ax = make_float4(0.f, 0.f, 0.f, 0.f);
    float4 rowi = make_float4(0.f, 0.f, 0.f, 0.f);
#pragma unroll
    for (int dr = -1; dr <= 2; dr++) {
        int r = i + dr;
        bool valid = (r >= 0 && r < 257);
        if (r == 256) r = 254;
        if (valid) {
            float4 t = ld4h(A + r * W_ + j0);
            ax.x += t.x; ax.y += t.y; ax.z += t.z; ax.w += t.w;
            if (dr == 0) rowi = t;
        }
    }

    float c7[7];
    c7[0] = (j0 > 0) ? __half2float(A[i * W_ + j0 - 1]) : 0.f;
    c7[1] = rowi.x; c7[2] = rowi.y; c7[3] = rowi.z; c7[4] = rowi.w;
    if (j0 < 252) {
        __half2 rr = *(const __half2*)(A + i * W_ + j0 + 4);
        float2 fr = __half22float2(rr);
        c7[5] = fr.x; c7[6] = fr.y;
    } else {
        c7[5] = rowi.z; c7[6] = 0.f;
    }
    float4 ay;
    ay.x = c7[0] + c7[1] + c7[2] + c7[3];
    ay.y = c7[1] + c7[2] + c7[3] + c7[4];
    ay.z = c7[2] + c7[3] + c7[4] + c7[5];
    ay.w = c7[3] + c7[4] + c7[5] + c7[6];

    float cv[4] = {0.f, 0.f, 0.f, 0.f};
#pragma unroll
    for (int dr = -1; dr <= 1; dr++) {
        int r = i + dr;
        if (r < 0 || r >= H_) continue;
        float w0 = __ldg(dw + c * 9 + (dr + 1) * 3 + 0);
        float w1 = __ldg(dw + c * 9 + (dr + 1) * 3 + 1);
        float w2 = __ldg(dw + c * 9 + (dr + 1) * 3 + 2);
        float cc[6];
        cc[0] = (j0 > 0) ? __half2float(VG[r * W_ + j0 - 1]) : 0.f;
        float4 ctr = ld4h(VG + r * W_ + j0);
        cc[1] = ctr.x; cc[2] = ctr.y; cc[3] = ctr.z; cc[4] = ctr.w;
        cc[5] = (j0 < 252) ? __half2float(VG[r * W_ + j0 + 4]) : 0.f;
#pragma unroll
        for (int l = 0; l < 4; l++)
            cv[l] = fmaf(w0, cc[l], fmaf(w1, cc[l + 1], fmaf(w2, cc[l + 2], cv[l])));
    }

    float4 v4 = ld4h(V + i * W_ + j0);
    float s  = __ldg(g + c) * rsqrtf(__ldg(vv + c) + 1e-5f);
    float tt = __ldg(bb + c) - __ldg(mm + c) * s;

    float rx = (ax.x + ay.x) * 0.25f + v4.x + fmaf(cv[0], s, tt);
    float ry = (ax.y + ay.y) * 0.25f + v4.y + fmaf(cv[1], s, tt);
    float rz = (ax.z + ay.z) * 0.25f + v4.z + fmaf(cv[2], s, tt);
    float rw = (ax.w + ay.w) * 0.25f + v4.w + fmaf(cv[3], s, tt);
    st4h(pre + (long long)bc * HW_ + i * W_ + j0, rx, ry, rz, rw);
}

// ---------------------------------------------------------------------------
extern "C" void kernel_launch(void* const* d_in, const int* in_sizes, int n_in,
                              void* d_out, int out_size)
{
    const float* x        = (const float*)d_in[0];
    const float* qkv_w    = (const float*)d_in[1];
    const float* qkv_b    = (const float*)d_in[2];
    const float* rel_tab  = (const float*)d_in[3];
    const float* gaze_pw  = (const float*)d_in[4];
    const float* gaze_dw  = (const float*)d_in[5];
    const float* gbn_g    = (const float*)d_in[6];
    const float* gbn_b    = (const float*)d_in[7];
    const float* gbn_m    = (const float*)d_in[8];
    const float* gbn_v    = (const float*)d_in[9];
    const float* proj_w   = (const float*)d_in[10];
    const float* pbn_g    = (const float*)d_in[11];
    const float* pbn_b    = (const float*)d_in[12];
    const float* pbn_m    = (const float*)d_in[13];
    const float* pbn_v    = (const float*)d_in[14];
    float* out = (float*)d_out;

    __half *qkvh, *attnh, *vgh, *preh, *xh, *wtq, *wtg, *wtp;
    cudaGetSymbolAddress((void**)&qkvh, d_qkvh_);
    cudaGetSymbolAddress((void**)&attnh, d_attnh_);
    cudaGetSymbolAddress((void**)&vgh, d_vgh_);
    cudaGetSymbolAddress((void**)&preh, d_preh_);
    cudaGetSymbolAddress((void**)&xh, d_xh_);
    cudaGetSymbolAddress((void**)&wtq, d_wtq_);
    cudaGetSymbolAddress((void**)&wtg, d_wtg_);
    cudaGetSymbolAddress((void**)&wtp, d_wtp_);

    const int SMEM = 65536;
    cudaFuncSetAttribute(gemm_h_kernel<0, true>, cudaFuncAttributeMaxDynamicSharedMemorySize, SMEM);
    cudaFuncSetAttribute(gemm_h_kernel<1, true>, cudaFuncAttributeMaxDynamicSharedMemorySize, SMEM);
    cudaFuncSetAttribute(gemm_h_kernel<2, false>, cudaFuncAttributeMaxDynamicSharedMemorySize, SMEM);
    cudaFuncSetAttribute(attn_kernel, cudaFuncAttributeMaxDynamicSharedMemorySize, SM_ATTN_TOTAL);

    // 0) pre-pass
    conv_x_kernel<<<(int)(((long long)B_ * C_ * HW_ / 4 + 255) / 256), 256>>>(
        x, xh, (long long)B_ * C_ * HW_ / 4);
    transw_kernel<<<(256 * 768 + 255) / 256, 256>>>(qkv_w, wtq, 768);
    transw_kernel<<<(256 * 256 + 255) / 256, 256>>>(gaze_pw, wtg, 256);
    transw_kernel<<<(256 * 256 + 255) / 256, 256>>>(proj_w, wtp, 256);

    // 1) qkv(fp16) = qkv_w @ x + b
    gemm_h_kernel<0, true><<<dim3(768 / 128, HW_ / 128, B_), 256, SMEM>>>(
        wtq, xh, qkvh, 768, (long long)C_ * HW_,
        qkv_b, nullptr, nullptr, nullptr, nullptr);

    // 2) window attention (HMMA)
    attn_kernel<<<dim3(1024, B_), 512, SM_ATTN_TOTAL>>>(qkvh, rel_tab, attnh);

    // 3) vg(fp16) = gaze_pw @ v (in-place slice of qkv)
    gemm_h_kernel<1, true><<<dim3(256 / 128, HW_ / 128, B_), 256, SMEM>>>(
        wtg, qkvh + (long long)512 * HW_, vgh, 256, (long long)768 * HW_,
        nullptr, nullptr, nullptr, nullptr, nullptr);

    // 4) pre(fp16) = (ax+ay)/4 + v + BN(dw3x3(vg))
    fuse_kernel<<<dim3(1, H_ / 4, B_ * C_), dim3(64, 4)>>>(
        attnh, qkvh, vgh, gaze_dw, gbn_g, gbn_b, gbn_m, gbn_v, preh);

    // 5) out(fp32) = BN(proj_w @ pre)
    gemm_h_kernel<2, false><<<dim3(256 / 128, HW_ / 128, B_), 256, SMEM>>>(
        wtp, preh, out, 256, (long long)C_ * HW_,
        nullptr, pbn_g, pbn_b, pbn_m, pbn_v);
}